// round 1
// baseline (speedup 1.0000x reference)
#include <cuda_runtime.h>
#include <math.h>
#include <stdint.h>

#define NHEADS 16
#define HDIM   128
#define CHUNK  64
#define BATCH  4
#define SEQ    4096
#define HID    2048
#define MROWS  (BATCH*SEQ)            /* 16384 */
#define QKV    (NHEADS*HDIM)          /* 2048  */

static __device__ float g_q  [(size_t)MROWS*QKV];
static __device__ float g_k  [(size_t)MROWS*QKV];
static __device__ float g_v  [(size_t)MROWS*QKV];
static __device__ float g_og [(size_t)MROWS*QKV];
static __device__ float g_ao [(size_t)MROWS*QKV];
static __device__ float g_beta[(size_t)MROWS*NHEADS];

// ---------------- packed f32x2 helpers (Blackwell FFMA2 path) ----------------
__device__ __forceinline__ unsigned long long pack2(float x, float y) {
    unsigned long long r;
    asm("mov.b64 %0, {%1, %2};" : "=l"(r) : "f"(x), "f"(y));
    return r;
}
__device__ __forceinline__ unsigned long long fma2(unsigned long long a,
                                                   unsigned long long b,
                                                   unsigned long long c) {
    unsigned long long d;
    asm("fma.rn.f32x2 %0, %1, %2, %3;" : "=l"(d) : "l"(a), "l"(b), "l"(c));
    return d;
}
__device__ __forceinline__ float2 unpack2(unsigned long long v) {
    float lo, hi;
    asm("mov.b64 {%0, %1}, %2;" : "=f"(lo), "=f"(hi) : "l"(v));
    return make_float2(lo, hi);
}

// ---------------------------------------------------------------------------
// Generic NT SGEMM: C[M,N] = A[M,K] @ W[N,K]^T + bias
// BM=BN=128, BK=8, 256 threads, 8x8 microtile, f32x2 packed FMA (pairs along M)
// ---------------------------------------------------------------------------
__global__ __launch_bounds__(256, 2)
void sgemm_nt(const float* __restrict__ A, const float* __restrict__ W,
              const float* __restrict__ bias, float* __restrict__ C,
              int M, int N, int K)
{
    constexpr int BM = 128, BN = 128, BK = 8, TM = 8, TN = 8;
    __shared__ float As[BK][BM];
    __shared__ float Bs[BK][BN];

    const int tid = threadIdx.x;
    const int tx  = tid & 15;         // 0..15 -> N microtile
    const int ty  = tid >> 4;         // 0..15 -> M microtile

    const int lrow = tid >> 1;        // 0..127
    const int lcol = (tid & 1) * 4;   // 0 or 4

    const float* Aptr = A + (size_t)(blockIdx.y * BM + lrow) * K + lcol;
    const float* Wptr = W + (size_t)(blockIdx.x * BN + lrow) * K + lcol;

    float4 aN = *(const float4*)(Aptr);
    float4 bN = *(const float4*)(Wptr);

    unsigned long long acc[TM/2][TN];
#pragma unroll
    for (int p = 0; p < TM/2; p++)
#pragma unroll
        for (int n = 0; n < TN; n++) acc[p][n] = 0ull;

    for (int k0 = 0; k0 < K; k0 += BK) {
        As[lcol+0][lrow] = aN.x; As[lcol+1][lrow] = aN.y;
        As[lcol+2][lrow] = aN.z; As[lcol+3][lrow] = aN.w;
        Bs[lcol+0][lrow] = bN.x; Bs[lcol+1][lrow] = bN.y;
        Bs[lcol+2][lrow] = bN.z; Bs[lcol+3][lrow] = bN.w;
        __syncthreads();

        if (k0 + BK < K) {
            aN = *(const float4*)(Aptr + k0 + BK);
            bN = *(const float4*)(Wptr + k0 + BK);
        }

#pragma unroll
        for (int kk = 0; kk < BK; kk++) {
            const unsigned long long* ap =
                (const unsigned long long*)&As[kk][ty * TM];
            unsigned long long a0 = ap[0], a1 = ap[1], a2 = ap[2], a3 = ap[3];
            const float* bp = &Bs[kk][tx * TN];
            float4 bv0 = *(const float4*)(bp);
            float4 bv1 = *(const float4*)(bp + 4);
            unsigned long long bd[TN];
            bd[0] = pack2(bv0.x, bv0.x); bd[1] = pack2(bv0.y, bv0.y);
            bd[2] = pack2(bv0.z, bv0.z); bd[3] = pack2(bv0.w, bv0.w);
            bd[4] = pack2(bv1.x, bv1.x); bd[5] = pack2(bv1.y, bv1.y);
            bd[6] = pack2(bv1.z, bv1.z); bd[7] = pack2(bv1.w, bv1.w);
#pragma unroll
            for (int n = 0; n < TN; n++) {
                acc[0][n] = fma2(a0, bd[n], acc[0][n]);
                acc[1][n] = fma2(a1, bd[n], acc[1][n]);
                acc[2][n] = fma2(a2, bd[n], acc[2][n]);
                acc[3][n] = fma2(a3, bd[n], acc[3][n]);
            }
        }
        __syncthreads();
    }

    // epilogue
    const size_t crow = (size_t)blockIdx.y * BM + ty * TM;
    const size_t ccol = (size_t)blockIdx.x * BN + tx * TN;
    float bv[TN];
#pragma unroll
    for (int n = 0; n < TN; n++) bv[n] = bias ? bias[ccol + n] : 0.0f;

#pragma unroll
    for (int p = 0; p < TM/2; p++) {
        float r0[TN], r1[TN];
#pragma unroll
        for (int n = 0; n < TN; n++) {
            float2 v = unpack2(acc[p][n]);
            r0[n] = v.x + bv[n];
            r1[n] = v.y + bv[n];
        }
        float* c0 = C + (crow + 2*p) * N + ccol;
        float* c1 = c0 + N;
        *(float4*)(c0)     = make_float4(r0[0], r0[1], r0[2], r0[3]);
        *(float4*)(c0 + 4) = make_float4(r0[4], r0[5], r0[6], r0[7]);
        *(float4*)(c1)     = make_float4(r1[0], r1[1], r1[2], r1[3]);
        *(float4*)(c1 + 4) = make_float4(r1[4], r1[5], r1[6], r1[7]);
    }
}

// ---------------------------------------------------------------------------
// beta = hs @ b_w^T + b_b  (N=16). One warp per row, coalesced float4 loads.
// ---------------------------------------------------------------------------
__global__ __launch_bounds__(256)
void beta_gemm(const float* __restrict__ hs, const float* __restrict__ bw,
               const float* __restrict__ bb, float* __restrict__ beta)
{
    int warp = (blockIdx.x * blockDim.x + threadIdx.x) >> 5;
    int lane = threadIdx.x & 31;
    if (warp >= MROWS) return;
    const float* x = hs + (size_t)warp * HID;

    float acc[NHEADS];
#pragma unroll
    for (int j = 0; j < NHEADS; j++) acc[j] = 0.0f;

    for (int t = 0; t < HID / 128; t++) {
        int k = t * 128 + lane * 4;
        float4 xv = *(const float4*)(x + k);
#pragma unroll
        for (int j = 0; j < NHEADS; j++) {
            float4 wv = *(const float4*)(bw + (size_t)j * HID + k);
            acc[j] += xv.x*wv.x + xv.y*wv.y + xv.z*wv.z + xv.w*wv.w;
        }
    }
#pragma unroll
    for (int j = 0; j < NHEADS; j++)
#pragma unroll
        for (int off = 16; off > 0; off >>= 1)
            acc[j] += __shfl_xor_sync(0xffffffffu, acc[j], off);

    if (lane < NHEADS) {
        float v = 0.0f;
#pragma unroll
        for (int j = 0; j < NHEADS; j++) if (lane == j) v = acc[j];
        beta[(size_t)warp * NHEADS + lane] = v + bb[lane];
    }
}

// ---------------------------------------------------------------------------
// pointwise: qn = l2norm(q/scale), kn = l2norm(k/scale), gv = softplus(beta)*v
// One warp per (b,l,head) row of 128; in place.
// ---------------------------------------------------------------------------
__global__ __launch_bounds__(256)
void pointwise_qkv(float* __restrict__ q, float* __restrict__ k,
                   float* __restrict__ v, const float* __restrict__ beta)
{
    int warp = (blockIdx.x * blockDim.x + threadIdx.x) >> 5;
    int lane = threadIdx.x & 31;
    size_t base = (size_t)warp * HDIM + lane * 4;
    const float inv_scale = 0.08838834764831845f;  // 1/sqrt(128)

    // q
    float4 qv = *(float4*)(q + base);
    float s = qv.x*qv.x + qv.y*qv.y + qv.z*qv.z + qv.w*qv.w;
#pragma unroll
    for (int off = 16; off > 0; off >>= 1) s += __shfl_xor_sync(~0u, s, off);
    float n  = sqrtf(s) * inv_scale;
    float f  = inv_scale / fmaxf(n, 1e-12f);
    qv.x *= f; qv.y *= f; qv.z *= f; qv.w *= f;
    *(float4*)(q + base) = qv;

    // k
    float4 kv = *(float4*)(k + base);
    s = kv.x*kv.x + kv.y*kv.y + kv.z*kv.z + kv.w*kv.w;
#pragma unroll
    for (int off = 16; off > 0; off >>= 1) s += __shfl_xor_sync(~0u, s, off);
    n = sqrtf(s) * inv_scale;
    f = inv_scale / fmaxf(n, 1e-12f);
    kv.x *= f; kv.y *= f; kv.z *= f; kv.w *= f;
    *(float4*)(k + base) = kv;

    // gv = softplus(beta) * v
    float b  = beta[warp];
    float sp = (b > 20.0f) ? b : log1pf(expf(b));
    float4 vv = *(float4*)(v + base);
    vv.x *= sp; vv.y *= sp; vv.z *= sp; vv.w *= sp;
    *(float4*)(v + base) = vv;
}

// ---------------------------------------------------------------------------
// Chunk attention: per (head, chunk, batch) block:
//   S = tril(Qc @ Kc^T)   (mask == lower-triangular ones, decay is identically 1)
//   O = S @ GVc
// Transposed+padded smem tiles for conflict-free microtiled FMA.
// ---------------------------------------------------------------------------
#define QK_PAD 68
__global__ __launch_bounds__(256)
void attn_kernel(const float* __restrict__ q, const float* __restrict__ k,
                 const float* __restrict__ gv, float* __restrict__ out)
{
    extern __shared__ float sm[];
    float* qT  = sm;                       // [128][QK_PAD]
    float* kT  = qT + 128 * QK_PAD;        // [128][QK_PAD]
    float* S   = kT + 128 * QK_PAD;        // [64][64]
    float* gvS = qT;                       // reuse qT region: [64][128]

    const int h  = blockIdx.x;
    const int cn = blockIdx.y;
    const int b  = blockIdx.z;
    const int tid = threadIdx.x;

    const size_t base =
        (((size_t)b * SEQ + (size_t)cn * CHUNK) * NHEADS + h) * HDIM;
    const int tokstride = NHEADS * HDIM;   // 2048

    // phase 1: load q,k transposed into smem
    for (int f = tid; f < 64 * 32; f += 256) {
        int row = f >> 5;
        int c4  = (f & 31) << 2;
        size_t g = base + (size_t)row * tokstride + c4;
        float4 qv4 = *(const float4*)(q + g);
        float4 kv4 = *(const float4*)(k + g);
        qT[(c4+0)*QK_PAD + row] = qv4.x; qT[(c4+1)*QK_PAD + row] = qv4.y;
        qT[(c4+2)*QK_PAD + row] = qv4.z; qT[(c4+3)*QK_PAD + row] = qv4.w;
        kT[(c4+0)*QK_PAD + row] = kv4.x; kT[(c4+1)*QK_PAD + row] = kv4.y;
        kT[(c4+2)*QK_PAD + row] = kv4.z; kT[(c4+3)*QK_PAD + row] = kv4.w;
    }
    __syncthreads();

    // phase 2: S[i][j] = sum_kk q[i][kk]*k[j][kk], masked to tril
    {
        const int tx = tid & 15, ty = tid >> 4;
        const int j0 = tx * 4, i0 = ty * 4;
        float acc[4][4] = {};
#pragma unroll 8
        for (int kk = 0; kk < 128; kk++) {
            float4 a = *(const float4*)&qT[kk * QK_PAD + i0];
            float4 bb4 = *(const float4*)&kT[kk * QK_PAD + j0];
            const float am[4] = {a.x, a.y, a.z, a.w};
            const float bm[4] = {bb4.x, bb4.y, bb4.z, bb4.w};
#pragma unroll
            for (int m = 0; m < 4; m++)
#pragma unroll
                for (int n = 0; n < 4; n++)
                    acc[m][n] += am[m] * bm[n];
        }
#pragma unroll
        for (int m = 0; m < 4; m++) {
            int i = i0 + m;
            float4 w;
            w.x = (j0 + 0 <= i) ? acc[m][0] : 0.0f;
            w.y = (j0 + 1 <= i) ? acc[m][1] : 0.0f;
            w.z = (j0 + 2 <= i) ? acc[m][2] : 0.0f;
            w.w = (j0 + 3 <= i) ? acc[m][3] : 0.0f;
            *(float4*)&S[i * 64 + j0] = w;
        }
    }
    __syncthreads();   // all reads of qT done before overwrite

    // load gv (natural layout) into the qT region
    for (int f = tid; f < 64 * 32; f += 256) {
        int row = f >> 5;
        int c4  = (f & 31) << 2;
        *(float4*)&gvS[row * 128 + c4] =
            *(const float4*)(gv + base + (size_t)row * tokstride + c4);
    }
    __syncthreads();

    // phase 3: O[i][:] = sum_{j<=i} S[i][j] * gv[j][:]
    {
        const int tx = tid & 15, ty = tid >> 4;
        const int kk0 = tx * 8, i0 = ty * 4;
        float o[4][8] = {};
        const int jend = i0 + 4;   // S is zero beyond the tile's diagonal band
        for (int j = 0; j < jend; j++) {
            float s0 = S[(i0+0)*64 + j];
            float s1 = S[(i0+1)*64 + j];
            float s2 = S[(i0+2)*64 + j];
            float s3 = S[(i0+3)*64 + j];
            float4 g0 = *(const float4*)&gvS[j * 128 + kk0];
            float4 g1 = *(const float4*)&gvS[j * 128 + kk0 + 4];
            const float gg[8] = {g0.x,g0.y,g0.z,g0.w,g1.x,g1.y,g1.z,g1.w};
#pragma unroll
            for (int n = 0; n < 8; n++) {
                o[0][n] += s0 * gg[n];
                o[1][n] += s1 * gg[n];
                o[2][n] += s2 * gg[n];
                o[3][n] += s3 * gg[n];
            }
        }
#pragma unroll
        for (int m = 0; m < 4; m++) {
            float* op = out + base + (size_t)(i0 + m) * tokstride + kk0;
            *(float4*)(op)     = make_float4(o[m][0], o[m][1], o[m][2], o[m][3]);
            *(float4*)(op + 4) = make_float4(o[m][4], o[m][5], o[m][6], o[m][7]);
        }
    }
}

// ---------------------------------------------------------------------------
// gated = attn_out * silu(og), written in place into og
// ---------------------------------------------------------------------------
__global__ __launch_bounds__(256)
void gate_kernel(const float* __restrict__ ao, float* __restrict__ og, size_t n4)
{
    size_t i = (size_t)blockIdx.x * blockDim.x + threadIdx.x;
    if (i >= n4) return;
    float4 a = ((const float4*)ao)[i];
    float4 g = ((float4*)og)[i];
    g.x = a.x * (g.x / (1.0f + expf(-g.x)));
    g.y = a.y * (g.y / (1.0f + expf(-g.y)));
    g.z = a.z * (g.z / (1.0f + expf(-g.z)));
    g.w = a.w * (g.w / (1.0f + expf(-g.w)));
    ((float4*)og)[i] = g;
}

// ---------------------------------------------------------------------------
extern "C" void kernel_launch(void* const* d_in, const int* in_sizes, int n_in,
                              void* d_out, int out_size)
{
    const float* hs   = (const float*)d_in[0];
    const float* q_w  = (const float*)d_in[1];
    const float* q_b  = (const float*)d_in[2];
    const float* k_w  = (const float*)d_in[3];
    const float* k_b  = (const float*)d_in[4];
    const float* v_w  = (const float*)d_in[5];
    const float* v_b  = (const float*)d_in[6];
    /* a_w = d_in[7], a_b = d_in[8]: dead code in reference */
    const float* b_w  = (const float*)d_in[9];
    const float* b_b  = (const float*)d_in[10];
    const float* og_w = (const float*)d_in[11];
    const float* o_w  = (const float*)d_in[12];
    const float* o_b  = (const float*)d_in[13];
    float* out = (float*)d_out;

    float *gq, *gk, *gv, *gog, *gao, *gbeta;
    cudaGetSymbolAddress((void**)&gq,    g_q);
    cudaGetSymbolAddress((void**)&gk,    g_k);
    cudaGetSymbolAddress((void**)&gv,    g_v);
    cudaGetSymbolAddress((void**)&gog,   g_og);
    cudaGetSymbolAddress((void**)&gao,   g_ao);
    cudaGetSymbolAddress((void**)&gbeta, g_beta);

    const int M = MROWS, N = QKV, K = HID;
    dim3 gGemm(N / 128, M / 128);   // (16, 128)

    sgemm_nt<<<gGemm, 256>>>(hs, q_w,  q_b,    gq,  M, N, K);
    sgemm_nt<<<gGemm, 256>>>(hs, k_w,  k_b,    gk,  M, N, K);
    sgemm_nt<<<gGemm, 256>>>(hs, v_w,  v_b,    gv,  M, N, K);
    sgemm_nt<<<gGemm, 256>>>(hs, og_w, nullptr, gog, M, N, K);

    beta_gemm<<<MROWS / 8, 256>>>(hs, b_w, b_b, gbeta);

    pointwise_qkv<<<(MROWS * NHEADS) / 8, 256>>>(gq, gk, gv, gbeta);

    size_t smemA = (size_t)(2 * 128 * QK_PAD + 64 * 64) * sizeof(float); // 86016
    cudaFuncSetAttribute(attn_kernel,
                         cudaFuncAttributeMaxDynamicSharedMemorySize,
                         (int)smemA);
    dim3 gAttn(NHEADS, SEQ / CHUNK, BATCH);  // (16, 64, 4)
    attn_kernel<<<gAttn, 256, smemA>>>(gq, gk, gv, gao);

    size_t n4 = (size_t)MROWS * QKV / 4;
    gate_kernel<<<(unsigned)(n4 / 256), 256>>>(gao, gog, n4);

    sgemm_nt<<<gGemm, 256>>>(gog, o_w, o_b, out, M, HID, QKV);
}

// round 7
// speedup vs baseline: 4.7349x; 4.7349x over previous
#include <cuda_runtime.h>
#include <cuda_bf16.h>
#include <math.h>
#include <stdint.h>

#define NHEADS 16
#define HDIM   128
#define CHUNK  64
#define BATCH  4
#define SEQ    4096
#define HID    2048
#define MROWS  (BATCH*SEQ)            /* 16384 */
#define QKV    (NHEADS*HDIM)          /* 2048  */
#define K3     (3*HID)                /* 6144  */

// ---------------- scratch (device globals; no allocation allowed) -----------
static __device__ float g_q  [(size_t)MROWS*QKV];
static __device__ float g_k  [(size_t)MROWS*QKV];
static __device__ float g_v  [(size_t)MROWS*QKV];
static __device__ float g_og [(size_t)MROWS*QKV];
static __device__ float g_ao [(size_t)MROWS*QKV];
static __device__ float g_beta[(size_t)MROWS*NHEADS];
static __device__ __nv_bfloat16 g_a1[(size_t)MROWS*K3];   // split activations
static __device__ __nv_bfloat16 g_wb[(size_t)QKV*K3];     // split weight buffer

// ---------------- PTX helpers (family-PTX-safe: sm_80-era only) -------------
__device__ __forceinline__ uint32_t smem_u32(const void* p) {
    uint32_t a;
    asm("{ .reg .u64 t; cvta.to.shared.u64 t, %1; cvt.u32.u64 %0, t; }"
        : "=r"(a) : "l"(p));
    return a;
}
__device__ __forceinline__ void cpa16(uint32_t d, const void* s) {
    asm volatile("cp.async.cg.shared.global [%0], [%1], 16;" :: "r"(d), "l"(s));
}
__device__ __forceinline__ void cp_commit() {
    asm volatile("cp.async.commit_group;" ::: "memory");
}
__device__ __forceinline__ void cp_wait2() {
    asm volatile("cp.async.wait_group 2;" ::: "memory");
}
__device__ __forceinline__ void ldsm4(uint32_t& r0, uint32_t& r1,
                                      uint32_t& r2, uint32_t& r3, uint32_t a) {
    asm volatile("ldmatrix.sync.aligned.m8n8.x4.shared.b16 {%0,%1,%2,%3}, [%4];"
                 : "=r"(r0), "=r"(r1), "=r"(r2), "=r"(r3) : "r"(a));
}
__device__ __forceinline__ void mma16816(float* c, const uint32_t* a,
                                         uint32_t b0, uint32_t b1) {
    asm volatile(
        "mma.sync.aligned.m16n8k16.row.col.f32.bf16.bf16.f32 "
        "{%0,%1,%2,%3}, {%4,%5,%6,%7}, {%8,%9}, {%0,%1,%2,%3};"
        : "+f"(c[0]), "+f"(c[1]), "+f"(c[2]), "+f"(c[3])
        : "r"(a[0]), "r"(a[1]), "r"(a[2]), "r"(a[3]), "r"(b0), "r"(b1));
}

// ---------------------------------------------------------------------------
// mma.sync bf16 GEMM: C[16384,2048] = A'[16384,K3] @ W'[2048,K3]^T (+bias)
// CTA tile 256x128, BK=64 bf16, 512 threads (16 warps, warp tile 64x32),
// 3-stage cp.async pipeline, SW128-swizzled smem, ldmatrix fragment loads.
// ---------------------------------------------------------------------------
#define GSTAGES   3
#define NCHUNK    (K3/64)            /* 96 */
#define A_BYTES   32768              /* 256 rows x 128B */
#define B_BYTES   16384              /* 128 rows x 128B */
#define STG_BYTES (A_BYTES + B_BYTES)
#define GSMEM     (GSTAGES*STG_BYTES)   /* 147456 */

__global__ __launch_bounds__(512, 1)
void gemm_bf16(const __nv_bfloat16* __restrict__ A,
               const __nv_bfloat16* __restrict__ B,
               const float* __restrict__ bias, float* __restrict__ C)
{
    extern __shared__ __align__(1024) char smem[];
    const uint32_t sb = smem_u32(smem);
    const int tid = threadIdx.x;
    const int bn0 = blockIdx.x * 128;
    const int bm0 = blockIdx.y * 256;

    // ---- loader geometry: 64 rows x 8 x 16B segments per pass ----
    const int r0  = tid >> 3;            // 0..63
    const int c16 = (tid & 7) * 16;      // byte offset within 128B row
    const size_t rowB = (size_t)K3 * 2;  // global row stride in bytes

    const char* abase = (const char*)A + (size_t)bm0 * rowB + c16;
    const char* bbase = (const char*)B + (size_t)bn0 * rowB + c16;

    auto load_stage = [&](int c, int s) {
        const uint32_t sA = sb + s * STG_BYTES;
        const uint32_t sBt = sA + A_BYTES;
        const char* ap = abase + (size_t)c * 128;
        const char* bp = bbase + (size_t)c * 128;
#pragma unroll
        for (int i = 0; i < 4; i++) {
            const int row = r0 + i * 64;
            uint32_t off = (uint32_t)row * 128 + (uint32_t)c16;
            uint32_t sw  = off ^ ((off >> 3) & 0x70);
            cpa16(sA + sw, ap + (size_t)row * rowB);
        }
#pragma unroll
        for (int i = 0; i < 2; i++) {
            const int row = r0 + i * 64;
            uint32_t off = (uint32_t)row * 128 + (uint32_t)c16;
            uint32_t sw  = off ^ ((off >> 3) & 0x70);
            cpa16(sBt + sw, bp + (size_t)row * rowB);
        }
        cp_commit();
    };

    // ---- warp fragment geometry ----
    const int lane = tid & 31;
    const int warp = tid >> 5;
    const int wm = warp >> 2;            // 0..3  -> 64-row block
    const int wn = warp & 3;             // 0..3  -> 32-col block

    // A ldmatrix address: row = wm*64 + mf*16 + (lane&15), colsel = (lane>>4)*16
    const int a_row  = wm * 64 + (lane & 15);
    const int a_sel  = (lane >> 4) * 16;
    const uint32_t a_x = (uint32_t)((a_row & 7) << 4);
    // B ldmatrix address: row = wn*32 + nb*16 + ((lane>>4)<<3) + (lane&7)
    const int b_row  = wn * 32 + ((lane >> 4) << 3) + (lane & 7);
    const int b_sel  = ((lane >> 3) & 1) * 16;
    const uint32_t b_x = (uint32_t)((b_row & 7) << 4);

    float acc[4][4][4];
#pragma unroll
    for (int i = 0; i < 4; i++)
#pragma unroll
        for (int j = 0; j < 4; j++)
#pragma unroll
            for (int r = 0; r < 4; r++) acc[i][j][r] = 0.0f;

    // prologue
    load_stage(0, 0);
    load_stage(1, 1);
    load_stage(2, 2);

    for (int c = 0; c < NCHUNK; c++) {
        const int s = c % GSTAGES;
        cp_wait2();
        __syncthreads();

        const uint32_t sA = sb + s * STG_BYTES;
        const uint32_t sBt = sA + A_BYTES;

#pragma unroll
        for (int ks = 0; ks < 4; ks++) {
            const uint32_t kb = (uint32_t)(ks * 32);
            // B frags: 2 x ldmatrix.x4 covering n32 x k16
            uint32_t b[2][4];
#pragma unroll
            for (int nb = 0; nb < 2; nb++) {
                uint32_t addr = sBt + (uint32_t)(b_row + nb * 16) * 128
                              + (((kb + (uint32_t)b_sel) ^ b_x));
                ldsm4(b[nb][0], b[nb][1], b[nb][2], b[nb][3], addr);
            }
            // A frags + mma
#pragma unroll
            for (int mf = 0; mf < 4; mf++) {
                uint32_t a[4];
                uint32_t addr = sA + (uint32_t)(a_row + mf * 16) * 128
                              + (((kb + (uint32_t)a_sel) ^ a_x));
                ldsm4(a[0], a[1], a[2], a[3], addr);
                mma16816(acc[mf][0], a, b[0][0], b[0][1]);
                mma16816(acc[mf][1], a, b[0][2], b[0][3]);
                mma16816(acc[mf][2], a, b[1][0], b[1][1]);
                mma16816(acc[mf][3], a, b[1][2], b[1][3]);
            }
        }
        __syncthreads();

        if (c + GSTAGES < NCHUNK) {
            load_stage(c + GSTAGES, s);
        } else {
            cp_commit();   // keep group count uniform for cp_wait2
        }
    }

    // ---- epilogue ----
#pragma unroll
    for (int nf = 0; nf < 4; nf++) {
        const int col = bn0 + wn * 32 + nf * 8 + (lane & 3) * 2;
        float b0 = 0.0f, b1 = 0.0f;
        if (bias) { b0 = bias[col]; b1 = bias[col + 1]; }
#pragma unroll
        for (int mf = 0; mf < 4; mf++) {
            const int row = bm0 + wm * 64 + mf * 16 + (lane >> 2);
            float2 v0 = make_float2(acc[mf][nf][0] + b0, acc[mf][nf][1] + b1);
            float2 v1 = make_float2(acc[mf][nf][2] + b0, acc[mf][nf][3] + b1);
            *(float2*)(C + (size_t)row * QKV + col)       = v0;
            *(float2*)(C + (size_t)(row + 8) * QKV + col) = v1;
        }
    }
}

// ---------------------------------------------------------------------------
// fp32 -> bf16 hi/lo split into K3 layout. lo_seg selects which 2048-col
// segment holds the lo part (others hold hi). act: lo_seg=2; weight: lo_seg=1.
// ---------------------------------------------------------------------------
__device__ __forceinline__ void split4(float4 v, uint2& hi, uint2& lo) {
    __nv_bfloat16 h0 = __float2bfloat16_rn(v.x);
    __nv_bfloat16 h1 = __float2bfloat16_rn(v.y);
    __nv_bfloat16 h2 = __float2bfloat16_rn(v.z);
    __nv_bfloat16 h3 = __float2bfloat16_rn(v.w);
    __nv_bfloat16 l0 = __float2bfloat16_rn(v.x - __bfloat162float(h0));
    __nv_bfloat16 l1 = __float2bfloat16_rn(v.y - __bfloat162float(h1));
    __nv_bfloat16 l2 = __float2bfloat16_rn(v.z - __bfloat162float(h2));
    __nv_bfloat16 l3 = __float2bfloat16_rn(v.w - __bfloat162float(h3));
    unsigned short u0 = *(unsigned short*)&h0, u1 = *(unsigned short*)&h1;
    unsigned short u2 = *(unsigned short*)&h2, u3 = *(unsigned short*)&h3;
    hi.x = (uint32_t)u0 | ((uint32_t)u1 << 16);
    hi.y = (uint32_t)u2 | ((uint32_t)u3 << 16);
    unsigned short w0 = *(unsigned short*)&l0, w1 = *(unsigned short*)&l1;
    unsigned short w2 = *(unsigned short*)&l2, w3 = *(unsigned short*)&l3;
    lo.x = (uint32_t)w0 | ((uint32_t)w1 << 16);
    lo.y = (uint32_t)w2 | ((uint32_t)w3 << 16);
}

__global__ __launch_bounds__(256)
void split3(const float* __restrict__ in, __nv_bfloat16* __restrict__ out, int lo_seg)
{
    size_t idx = (size_t)blockIdx.x * 256 + threadIdx.x;
    size_t row = idx >> 9;
    int c4 = (int)(idx & 511) << 2;
    float4 v = *(const float4*)(in + row * 2048 + c4);
    uint2 hi, lo;
    split4(v, hi, lo);
    uint2* o = (uint2*)(out + row * K3 + c4);
#pragma unroll
    for (int s = 0; s < 3; s++)
        o[(size_t)s * 512] = (s == lo_seg) ? lo : hi;   // 512 uint2 = 2048 bf16
}

// gated = ao * silu(og), directly split into activation buffer (hi,hi,lo)
__global__ __launch_bounds__(256)
void gate_split(const float* __restrict__ ao, const float* __restrict__ og,
                __nv_bfloat16* __restrict__ out)
{
    size_t idx = (size_t)blockIdx.x * 256 + threadIdx.x;
    size_t row = idx >> 9;
    int c4 = (int)(idx & 511) << 2;
    float4 a = *(const float4*)(ao + row * 2048 + c4);
    float4 g = *(const float4*)(og + row * 2048 + c4);
    float4 y;
    y.x = a.x * (g.x / (1.0f + expf(-g.x)));
    y.y = a.y * (g.y / (1.0f + expf(-g.y)));
    y.z = a.z * (g.z / (1.0f + expf(-g.z)));
    y.w = a.w * (g.w / (1.0f + expf(-g.w)));
    uint2 hi, lo;
    split4(y, hi, lo);
    uint2* o = (uint2*)(out + row * K3 + c4);
    o[0]    = hi;
    o[512]  = hi;
    o[1024] = lo;
}

// ---------------------------------------------------------------------------
// beta = hs @ b_w^T + b_b  (N=16)
// ---------------------------------------------------------------------------
__global__ __launch_bounds__(256)
void beta_gemm(const float* __restrict__ hs, const float* __restrict__ bw,
               const float* __restrict__ bb, float* __restrict__ beta)
{
    int warp = (blockIdx.x * blockDim.x + threadIdx.x) >> 5;
    int lane = threadIdx.x & 31;
    if (warp >= MROWS) return;
    const float* x = hs + (size_t)warp * HID;

    float acc[NHEADS];
#pragma unroll
    for (int j = 0; j < NHEADS; j++) acc[j] = 0.0f;

    for (int t = 0; t < HID / 128; t++) {
        int k = t * 128 + lane * 4;
        float4 xv = *(const float4*)(x + k);
#pragma unroll
        for (int j = 0; j < NHEADS; j++) {
            float4 wv = *(const float4*)(bw + (size_t)j * HID + k);
            acc[j] += xv.x*wv.x + xv.y*wv.y + xv.z*wv.z + xv.w*wv.w;
        }
    }
#pragma unroll
    for (int j = 0; j < NHEADS; j++)
#pragma unroll
        for (int off = 16; off > 0; off >>= 1)
            acc[j] += __shfl_xor_sync(0xffffffffu, acc[j], off);

    if (lane < NHEADS) {
        float v = 0.0f;
#pragma unroll
        for (int j = 0; j < NHEADS; j++) if (lane == j) v = acc[j];
        beta[(size_t)warp * NHEADS + lane] = v + bb[lane];
    }
}

// ---------------------------------------------------------------------------
// pointwise: qn = l2norm(q/scale), kn = l2norm(k/scale), gv = softplus(beta)*v
// ---------------------------------------------------------------------------
__global__ __launch_bounds__(256)
void pointwise_qkv(float* __restrict__ q, float* __restrict__ k,
                   float* __restrict__ v, const float* __restrict__ beta)
{
    int warp = (blockIdx.x * blockDim.x + threadIdx.x) >> 5;
    int lane = threadIdx.x & 31;
    size_t base = (size_t)warp * HDIM + lane * 4;
    const float inv_scale = 0.08838834764831845f;

    float4 qv = *(float4*)(q + base);
    float s = qv.x*qv.x + qv.y*qv.y + qv.z*qv.z + qv.w*qv.w;
#pragma unroll
    for (int off = 16; off > 0; off >>= 1) s += __shfl_xor_sync(~0u, s, off);
    float n = sqrtf(s) * inv_scale;
    float f = inv_scale / fmaxf(n, 1e-12f);
    qv.x *= f; qv.y *= f; qv.z *= f; qv.w *= f;
    *(float4*)(q + base) = qv;

    float4 kv = *(float4*)(k + base);
    s = kv.x*kv.x + kv.y*kv.y + kv.z*kv.z + kv.w*kv.w;
#pragma unroll
    for (int off = 16; off > 0; off >>= 1) s += __shfl_xor_sync(~0u, s, off);
    n = sqrtf(s) * inv_scale;
    f = inv_scale / fmaxf(n, 1e-12f);
    kv.x *= f; kv.y *= f; kv.z *= f; kv.w *= f;
    *(float4*)(k + base) = kv;

    float b  = beta[warp];
    float sp = (b > 20.0f) ? b : log1pf(expf(b));
    float4 vv = *(float4*)(v + base);
    vv.x *= sp; vv.y *= sp; vv.z *= sp; vv.w *= sp;
    *(float4*)(v + base) = vv;
}

// ---------------------------------------------------------------------------
// Chunk attention (mask == tril of ones since decay = exp(-0.1*clip(j-i,0)) = 1
// on the kept region):  S = tril(Qc Kc^T);  O = S @ GVc
// ---------------------------------------------------------------------------
#define QK_PAD 68
__global__ __launch_bounds__(256)
void attn_kernel(const float* __restrict__ q, const float* __restrict__ k,
                 const float* __restrict__ gv, float* __restrict__ out)
{
    extern __shared__ float sm[];
    float* qT  = sm;
    float* kT  = qT + 128 * QK_PAD;
    float* S   = kT + 128 * QK_PAD;
    float* gvS = qT;

    const int h  = blockIdx.x;
    const int cn = blockIdx.y;
    const int b  = blockIdx.z;
    const int tid = threadIdx.x;

    const size_t base =
        (((size_t)b * SEQ + (size_t)cn * CHUNK) * NHEADS + h) * HDIM;
    const int tokstride = NHEADS * HDIM;

    for (int f = tid; f < 64 * 32; f += 256) {
        int row = f >> 5;
        int c4  = (f & 31) << 2;
        size_t g = base + (size_t)row * tokstride + c4;
        float4 qv4 = *(const float4*)(q + g);
        float4 kv4 = *(const float4*)(k + g);
        qT[(c4+0)*QK_PAD + row] = qv4.x; qT[(c4+1)*QK_PAD + row] = qv4.y;
        qT[(c4+2)*QK_PAD + row] = qv4.z; qT[(c4+3)*QK_PAD + row] = qv4.w;
        kT[(c4+0)*QK_PAD + row] = kv4.x; kT[(c4+1)*QK_PAD + row] = kv4.y;
        kT[(c4+2)*QK_PAD + row] = kv4.z; kT[(c4+3)*QK_PAD + row] = kv4.w;
    }
    __syncthreads();

    {
        const int tx = tid & 15, ty = tid >> 4;
        const int j0 = tx * 4, i0 = ty * 4;
        float acc[4][4] = {};
#pragma unroll 8
        for (int kk = 0; kk < 128; kk++) {
            float4 a = *(const float4*)&qT[kk * QK_PAD + i0];
            float4 bb4 = *(const float4*)&kT[kk * QK_PAD + j0];
            const float am[4] = {a.x, a.y, a.z, a.w};
            const float bm[4] = {bb4.x, bb4.y, bb4.z, bb4.w};
#pragma unroll
            for (int m = 0; m < 4; m++)
#pragma unroll
                for (int n = 0; n < 4; n++)
                    acc[m][n] += am[m] * bm[n];
        }
#pragma unroll
        for (int m = 0; m < 4; m++) {
            int i = i0 + m;
            float4 w;
            w.x = (j0 + 0 <= i) ? acc[m][0] : 0.0f;
            w.y = (j0 + 1 <= i) ? acc[m][1] : 0.0f;
            w.z = (j0 + 2 <= i) ? acc[m][2] : 0.0f;
            w.w = (j0 + 3 <= i) ? acc[m][3] : 0.0f;
            *(float4*)&S[i * 64 + j0] = w;
        }
    }
    __syncthreads();

    for (int f = tid; f < 64 * 32; f += 256) {
        int row = f >> 5;
        int c4  = (f & 31) << 2;
        *(float4*)&gvS[row * 128 + c4] =
            *(const float4*)(gv + base + (size_t)row * tokstride + c4);
    }
    __syncthreads();

    {
        const int tx = tid & 15, ty = tid >> 4;
        const int kk0 = tx * 8, i0 = ty * 4;
        float o[4][8] = {};
        const int jend = i0 + 4;
        for (int j = 0; j < jend; j++) {
            float s0 = S[(i0+0)*64 + j];
            float s1 = S[(i0+1)*64 + j];
            float s2 = S[(i0+2)*64 + j];
            float s3 = S[(i0+3)*64 + j];
            float4 g0 = *(const float4*)&gvS[j * 128 + kk0];
            float4 g1 = *(const float4*)&gvS[j * 128 + kk0 + 4];
            const float gg[8] = {g0.x,g0.y,g0.z,g0.w,g1.x,g1.y,g1.z,g1.w};
#pragma unroll
            for (int n = 0; n < 8; n++) {
                o[0][n] += s0 * gg[n];
                o[1][n] += s1 * gg[n];
                o[2][n] += s2 * gg[n];
                o[3][n] += s3 * gg[n];
            }
        }
#pragma unroll
        for (int m = 0; m < 4; m++) {
            float* op = out + base + (size_t)(i0 + m) * tokstride + kk0;
            *(float4*)(op)     = make_float4(o[m][0], o[m][1], o[m][2], o[m][3]);
            *(float4*)(op + 4) = make_float4(o[m][4], o[m][5], o[m][6], o[m][7]);
        }
    }
}

// ---------------------------------------------------------------------------
extern "C" void kernel_launch(void* const* d_in, const int* in_sizes, int n_in,
                              void* d_out, int out_size)
{
    const float* hs   = (const float*)d_in[0];
    const float* q_w  = (const float*)d_in[1];
    const float* q_b  = (const float*)d_in[2];
    const float* k_w  = (const float*)d_in[3];
    const float* k_b  = (const float*)d_in[4];
    const float* v_w  = (const float*)d_in[5];
    const float* v_b  = (const float*)d_in[6];
    /* a_w, a_b (d_in[7], d_in[8]) are dead code in the reference */
    const float* b_w  = (const float*)d_in[9];
    const float* b_b  = (const float*)d_in[10];
    const float* og_w = (const float*)d_in[11];
    const float* o_w  = (const float*)d_in[12];
    const float* o_b  = (const float*)d_in[13];
    float* out = (float*)d_out;

    float *gq, *gk, *gv, *gog, *gao, *gbeta;
    __nv_bfloat16 *ga1, *gwb;
    cudaGetSymbolAddress((void**)&gq,    g_q);
    cudaGetSymbolAddress((void**)&gk,    g_k);
    cudaGetSymbolAddress((void**)&gv,    g_v);
    cudaGetSymbolAddress((void**)&gog,   g_og);
    cudaGetSymbolAddress((void**)&gao,   g_ao);
    cudaGetSymbolAddress((void**)&gbeta, g_beta);
    cudaGetSymbolAddress((void**)&ga1,   g_a1);
    cudaGetSymbolAddress((void**)&gwb,   g_wb);

    cudaFuncSetAttribute(gemm_bf16,
                         cudaFuncAttributeMaxDynamicSharedMemorySize, GSMEM);

    const dim3 gG(QKV / 128, MROWS / 256);        // (16, 64)
    const unsigned actBlocks = (unsigned)((size_t)MROWS * 512 / 256);  // 32768
    const unsigned wBlocks   = (unsigned)((size_t)QKV  * 512 / 256);   // 4096

    // split activations once (hi,hi,lo)
    split3<<<actBlocks, 256>>>(hs, ga1, 2);

    // q,k,v,og projections
    split3<<<wBlocks, 256>>>(q_w,  gwb, 1);
    gemm_bf16<<<gG, 512, GSMEM>>>(ga1, gwb, q_b, gq);
    split3<<<wBlocks, 256>>>(k_w,  gwb, 1);
    gemm_bf16<<<gG, 512, GSMEM>>>(ga1, gwb, k_b, gk);
    split3<<<wBlocks, 256>>>(v_w,  gwb, 1);
    gemm_bf16<<<gG, 512, GSMEM>>>(ga1, gwb, v_b, gv);
    split3<<<wBlocks, 256>>>(og_w, gwb, 1);
    gemm_bf16<<<gG, 512, GSMEM>>>(ga1, gwb, nullptr, gog);

    beta_gemm<<<MROWS / 8, 256>>>(hs, b_w, b_b, gbeta);
    pointwise_qkv<<<(MROWS * NHEADS) / 8, 256>>>(gq, gk, gv, gbeta);

    size_t smemA = (size_t)(2 * 128 * QK_PAD + 64 * 64) * sizeof(float);
    cudaFuncSetAttribute(attn_kernel,
                         cudaFuncAttributeMaxDynamicSharedMemorySize, (int)smemA);
    dim3 gAttn(NHEADS, SEQ / CHUNK, BATCH);
    attn_kernel<<<gAttn, 256, smemA>>>(gq, gk, gv, gao);

    // gate + split gated activations (reuses ga1), then output projection
    gate_split<<<actBlocks, 256>>>(gao, gog, ga1);
    split3<<<wBlocks, 256>>>(o_w, gwb, 1);
    gemm_bf16<<<gG, 512, GSMEM>>>(ga1, gwb, o_b, out);
}

// round 8
// speedup vs baseline: 5.5035x; 1.1623x over previous
#include <cuda_runtime.h>
#include <cuda_bf16.h>
#include <math.h>
#include <stdint.h>

#define NHEADS 16
#define HDIM   128
#define CHUNK  64
#define BATCH  4
#define SEQ    4096
#define HID    2048
#define MROWS  (BATCH*SEQ)            /* 16384 */
#define QKV    (NHEADS*HDIM)          /* 2048  */
#define K2     (2*HID)                /* 4096: [hi | lo] */

// ---------------- scratch (device globals; no allocation allowed) -----------
static __device__ float g_q  [(size_t)MROWS*QKV];
static __device__ float g_k  [(size_t)MROWS*QKV];
static __device__ float g_v  [(size_t)MROWS*QKV];
static __device__ float g_og [(size_t)MROWS*QKV];
static __device__ float g_ao [(size_t)MROWS*QKV];
static __device__ float g_beta[(size_t)MROWS*NHEADS];
static __device__ __nv_bfloat16 g_a1[(size_t)MROWS*K2];   // split activations
static __device__ __nv_bfloat16 g_wb[(size_t)QKV*K2];     // split weight buffer

// ---------------- PTX helpers (family-PTX-safe: sm_80-era only) -------------
__device__ __forceinline__ uint32_t smem_u32(const void* p) {
    uint32_t a;
    asm("{ .reg .u64 t; cvta.to.shared.u64 t, %1; cvt.u32.u64 %0, t; }"
        : "=r"(a) : "l"(p));
    return a;
}
__device__ __forceinline__ void cpa16(uint32_t d, const void* s) {
    asm volatile("cp.async.cg.shared.global [%0], [%1], 16;" :: "r"(d), "l"(s));
}
__device__ __forceinline__ void cp_commit() {
    asm volatile("cp.async.commit_group;" ::: "memory");
}
__device__ __forceinline__ void cp_wait1() {
    asm volatile("cp.async.wait_group 1;" ::: "memory");
}
__device__ __forceinline__ void ldsm4(uint32_t& r0, uint32_t& r1,
                                      uint32_t& r2, uint32_t& r3, uint32_t a) {
    asm volatile("ldmatrix.sync.aligned.m8n8.x4.shared.b16 {%0,%1,%2,%3}, [%4];"
                 : "=r"(r0), "=r"(r1), "=r"(r2), "=r"(r3) : "r"(a));
}
__device__ __forceinline__ void mma16816(float* c, const uint32_t* a,
                                         uint32_t b0, uint32_t b1) {
    asm volatile(
        "mma.sync.aligned.m16n8k16.row.col.f32.bf16.bf16.f32 "
        "{%0,%1,%2,%3}, {%4,%5,%6,%7}, {%8,%9}, {%0,%1,%2,%3};"
        : "+f"(c[0]), "+f"(c[1]), "+f"(c[2]), "+f"(c[3])
        : "r"(a[0]), "r"(a[1]), "r"(a[2]), "r"(a[3]), "r"(b0), "r"(b1));
}

// ---------------------------------------------------------------------------
// mma.sync bf16 GEMM with 3-product hi/lo split from [hi|lo] storage:
//   C = Ahi*Whi^T + Ahi*Wlo^T + Alo*Whi^T  (+bias)
// CTA tile 256x128, 512 threads (16 warps, warp tile 64x32).
// 32 super-chunks of 64 cols; per stage: Ahi,Alo (32KB each) + Whi,Wlo (16KB
// each) = 96KB; 2-stage cp.async pipeline (192KB smem).
// ---------------------------------------------------------------------------
#define NSC      32
#define OFF_AHI  0
#define OFF_ALO  32768
#define OFF_WHI  65536
#define OFF_WLO  81920
#define STG_BYTES 98304
#define GSMEM    (2*STG_BYTES)          /* 196608 */

__global__ __launch_bounds__(512, 1)
void gemm_bf16(const __nv_bfloat16* __restrict__ A,
               const __nv_bfloat16* __restrict__ B,
               const float* __restrict__ bias, float* __restrict__ C)
{
    extern __shared__ __align__(1024) char smem[];
    const uint32_t sb = smem_u32(smem);
    const int tid = threadIdx.x;
    const int bn0 = blockIdx.x * 128;
    const int bm0 = blockIdx.y * 256;

    // ---- loader geometry ----
    const int r0  = tid >> 3;            // 0..63
    const int c16 = (tid & 7) * 16;      // byte offset within 128B row
    const size_t rowB = (size_t)K2 * 2;  // 8192 bytes global row stride

    const char* abase = (const char*)A + (size_t)bm0 * rowB + c16;
    const char* bbase = (const char*)B + (size_t)bn0 * rowB + c16;

    auto load_stage = [&](int sc, int s) {
        const uint32_t st = sb + s * STG_BYTES;
        const char* ap = abase + (size_t)sc * 128;
        const char* bp = bbase + (size_t)sc * 128;
#pragma unroll
        for (int i = 0; i < 4; i++) {
            const int row = r0 + i * 64;
            uint32_t off = (uint32_t)row * 128 + (uint32_t)c16;
            uint32_t sw  = off ^ ((off >> 3) & 0x70);
            const char* g = ap + (size_t)row * rowB;
            cpa16(st + OFF_AHI + sw, g);
            cpa16(st + OFF_ALO + sw, g + 4096);   // lo segment: +2048 bf16
        }
#pragma unroll
        for (int i = 0; i < 2; i++) {
            const int row = r0 + i * 64;
            uint32_t off = (uint32_t)row * 128 + (uint32_t)c16;
            uint32_t sw  = off ^ ((off >> 3) & 0x70);
            const char* g = bp + (size_t)row * rowB;
            cpa16(st + OFF_WHI + sw, g);
            cpa16(st + OFF_WLO + sw, g + 4096);
        }
        cp_commit();
    };

    // ---- warp fragment geometry ----
    const int lane = tid & 31;
    const int warp = tid >> 5;
    const int wm = warp >> 2;            // 0..3  -> 64-row block
    const int wn = warp & 3;             // 0..3  -> 32-col block

    const int a_row  = wm * 64 + (lane & 15);
    const int a_sel  = (lane >> 4) * 16;
    const uint32_t a_x = (uint32_t)((a_row & 7) << 4);
    const int b_row  = wn * 32 + ((lane >> 4) << 3) + (lane & 7);
    const int b_sel  = ((lane >> 3) & 1) * 16;
    const uint32_t b_x = (uint32_t)((b_row & 7) << 4);

    float acc[4][4][4];
#pragma unroll
    for (int i = 0; i < 4; i++)
#pragma unroll
        for (int j = 0; j < 4; j++)
#pragma unroll
            for (int r = 0; r < 4; r++) acc[i][j][r] = 0.0f;

    // prologue
    load_stage(0, 0);
    load_stage(1, 1);

    for (int sc = 0; sc < NSC; sc++) {
        const int s = sc & 1;
        cp_wait1();
        __syncthreads();

        const uint32_t st = sb + s * STG_BYTES;

#pragma unroll
        for (int ks = 0; ks < 4; ks++) {
            const uint32_t kb = (uint32_t)(ks * 32);
            uint32_t bhi[2][4], blo[2][4];
#pragma unroll
            for (int nb = 0; nb < 2; nb++) {
                uint32_t broff = (uint32_t)(b_row + nb * 16) * 128
                               + ((kb + (uint32_t)b_sel) ^ b_x);
                ldsm4(bhi[nb][0], bhi[nb][1], bhi[nb][2], bhi[nb][3],
                      st + OFF_WHI + broff);
                ldsm4(blo[nb][0], blo[nb][1], blo[nb][2], blo[nb][3],
                      st + OFF_WLO + broff);
            }
#pragma unroll
            for (int mf = 0; mf < 4; mf++) {
                uint32_t aroff = (uint32_t)(a_row + mf * 16) * 128
                               + ((kb + (uint32_t)a_sel) ^ a_x);
                uint32_t a[4];
                // Ahi * Whi  and  Ahi * Wlo
                ldsm4(a[0], a[1], a[2], a[3], st + OFF_AHI + aroff);
                mma16816(acc[mf][0], a, bhi[0][0], bhi[0][1]);
                mma16816(acc[mf][1], a, bhi[0][2], bhi[0][3]);
                mma16816(acc[mf][2], a, bhi[1][0], bhi[1][1]);
                mma16816(acc[mf][3], a, bhi[1][2], bhi[1][3]);
                mma16816(acc[mf][0], a, blo[0][0], blo[0][1]);
                mma16816(acc[mf][1], a, blo[0][2], blo[0][3]);
                mma16816(acc[mf][2], a, blo[1][0], blo[1][1]);
                mma16816(acc[mf][3], a, blo[1][2], blo[1][3]);
                // Alo * Whi
                ldsm4(a[0], a[1], a[2], a[3], st + OFF_ALO + aroff);
                mma16816(acc[mf][0], a, bhi[0][0], bhi[0][1]);
                mma16816(acc[mf][1], a, bhi[0][2], bhi[0][3]);
                mma16816(acc[mf][2], a, bhi[1][0], bhi[1][1]);
                mma16816(acc[mf][3], a, bhi[1][2], bhi[1][3]);
            }
        }
        __syncthreads();

        if (sc + 2 < NSC) {
            load_stage(sc + 2, s);
        } else {
            cp_commit();   // keep group count uniform for cp_wait1
        }
    }

    // ---- epilogue ----
#pragma unroll
    for (int nf = 0; nf < 4; nf++) {
        const int col = bn0 + wn * 32 + nf * 8 + (lane & 3) * 2;
        float b0 = 0.0f, b1 = 0.0f;
        if (bias) { b0 = bias[col]; b1 = bias[col + 1]; }
#pragma unroll
        for (int mf = 0; mf < 4; mf++) {
            const int row = bm0 + wm * 64 + mf * 16 + (lane >> 2);
            float2 v0 = make_float2(acc[mf][nf][0] + b0, acc[mf][nf][1] + b1);
            float2 v1 = make_float2(acc[mf][nf][2] + b0, acc[mf][nf][3] + b1);
            *(float2*)(C + (size_t)row * QKV + col)       = v0;
            *(float2*)(C + (size_t)(row + 8) * QKV + col) = v1;
        }
    }
}

// ---------------------------------------------------------------------------
// fp32 -> bf16 hi/lo split into [hi | lo] K2 layout.
// ---------------------------------------------------------------------------
__device__ __forceinline__ void split4(float4 v, uint2& hi, uint2& lo) {
    __nv_bfloat16 h0 = __float2bfloat16_rn(v.x);
    __nv_bfloat16 h1 = __float2bfloat16_rn(v.y);
    __nv_bfloat16 h2 = __float2bfloat16_rn(v.z);
    __nv_bfloat16 h3 = __float2bfloat16_rn(v.w);
    __nv_bfloat16 l0 = __float2bfloat16_rn(v.x - __bfloat162float(h0));
    __nv_bfloat16 l1 = __float2bfloat16_rn(v.y - __bfloat162float(h1));
    __nv_bfloat16 l2 = __float2bfloat16_rn(v.z - __bfloat162float(h2));
    __nv_bfloat16 l3 = __float2bfloat16_rn(v.w - __bfloat162float(h3));
    unsigned short u0 = *(unsigned short*)&h0, u1 = *(unsigned short*)&h1;
    unsigned short u2 = *(unsigned short*)&h2, u3 = *(unsigned short*)&h3;
    hi.x = (uint32_t)u0 | ((uint32_t)u1 << 16);
    hi.y = (uint32_t)u2 | ((uint32_t)u3 << 16);
    unsigned short w0 = *(unsigned short*)&l0, w1 = *(unsigned short*)&l1;
    unsigned short w2 = *(unsigned short*)&l2, w3 = *(unsigned short*)&l3;
    lo.x = (uint32_t)w0 | ((uint32_t)w1 << 16);
    lo.y = (uint32_t)w2 | ((uint32_t)w3 << 16);
}

__global__ __launch_bounds__(256)
void split2(const float* __restrict__ in, __nv_bfloat16* __restrict__ out)
{
    size_t idx = (size_t)blockIdx.x * 256 + threadIdx.x;
    size_t row = idx >> 9;
    int c4 = (int)(idx & 511) << 2;
    float4 v = *(const float4*)(in + row * 2048 + c4);
    uint2 hi, lo;
    split4(v, hi, lo);
    uint2* o = (uint2*)(out + row * K2 + c4);
    o[0]   = hi;
    o[512] = lo;            // +2048 bf16
}

// gated = ao * silu(og), directly split into activation buffer [hi|lo]
__global__ __launch_bounds__(256)
void gate_split(const float* __restrict__ ao, const float* __restrict__ og,
                __nv_bfloat16* __restrict__ out)
{
    size_t idx = (size_t)blockIdx.x * 256 + threadIdx.x;
    size_t row = idx >> 9;
    int c4 = (int)(idx & 511) << 2;
    float4 a = *(const float4*)(ao + row * 2048 + c4);
    float4 g = *(const float4*)(og + row * 2048 + c4);
    float4 y;
    y.x = a.x * (g.x / (1.0f + expf(-g.x)));
    y.y = a.y * (g.y / (1.0f + expf(-g.y)));
    y.z = a.z * (g.z / (1.0f + expf(-g.z)));
    y.w = a.w * (g.w / (1.0f + expf(-g.w)));
    uint2 hi, lo;
    split4(y, hi, lo);
    uint2* o = (uint2*)(out + row * K2 + c4);
    o[0]   = hi;
    o[512] = lo;
}

// ---------------------------------------------------------------------------
// beta = hs @ b_w^T + b_b  (N=16)
// ---------------------------------------------------------------------------
__global__ __launch_bounds__(256)
void beta_gemm(const float* __restrict__ hs, const float* __restrict__ bw,
               const float* __restrict__ bb, float* __restrict__ beta)
{
    int warp = (blockIdx.x * blockDim.x + threadIdx.x) >> 5;
    int lane = threadIdx.x & 31;
    if (warp >= MROWS) return;
    const float* x = hs + (size_t)warp * HID;

    float acc[NHEADS];
#pragma unroll
    for (int j = 0; j < NHEADS; j++) acc[j] = 0.0f;

    for (int t = 0; t < HID / 128; t++) {
        int k = t * 128 + lane * 4;
        float4 xv = *(const float4*)(x + k);
#pragma unroll
        for (int j = 0; j < NHEADS; j++) {
            float4 wv = *(const float4*)(bw + (size_t)j * HID + k);
            acc[j] += xv.x*wv.x + xv.y*wv.y + xv.z*wv.z + xv.w*wv.w;
        }
    }
#pragma unroll
    for (int j = 0; j < NHEADS; j++)
#pragma unroll
        for (int off = 16; off > 0; off >>= 1)
            acc[j] += __shfl_xor_sync(0xffffffffu, acc[j], off);

    if (lane < NHEADS) {
        float v = 0.0f;
#pragma unroll
        for (int j = 0; j < NHEADS; j++) if (lane == j) v = acc[j];
        beta[(size_t)warp * NHEADS + lane] = v + bb[lane];
    }
}

// ---------------------------------------------------------------------------
// Chunk attention with FUSED pointwise:
//   qn = l2norm(q/scale), kn = l2norm(k/scale) computed during the transposed
//   smem load (one warp owns each token row -> shfl reduction);
//   gv = softplus(beta)*v applied during the gv load.
//   S = tril(Qc Kc^T) (decay==1 on kept region); O = S @ GVc.
// ---------------------------------------------------------------------------
#define QK_PAD 68
__global__ __launch_bounds__(256)
void attn_kernel(const float* __restrict__ q, const float* __restrict__ k,
                 const float* __restrict__ v, const float* __restrict__ beta,
                 float* __restrict__ out)
{
    extern __shared__ float sm[];
    float* qT  = sm;
    float* kT  = qT + 128 * QK_PAD;
    float* S   = kT + 128 * QK_PAD;
    float* gvS = qT;

    const int h  = blockIdx.x;
    const int cn = blockIdx.y;
    const int b  = blockIdx.z;
    const int tid = threadIdx.x;
    const int lane = tid & 31;

    const size_t tok0 = (size_t)b * SEQ + (size_t)cn * CHUNK;
    const size_t base = (tok0 * NHEADS + h) * HDIM;
    const int tokstride = NHEADS * HDIM;
    const float eps_n = 1.1313708499e-11f;   // sqrt(128) * 1e-12

    // phase 1: load q,k; per-row l2 normalization via warp shfl reduction
    for (int f = tid; f < 64 * 32; f += 256) {
        int row = f >> 5;            // warp-uniform: row = warp + 8*iter
        int c4  = (f & 31) << 2;     // lane*4
        size_t g = base + (size_t)row * tokstride + c4;
        float4 qv4 = *(const float4*)(q + g);
        float4 kv4 = *(const float4*)(k + g);

        float sq = qv4.x*qv4.x + qv4.y*qv4.y + qv4.z*qv4.z + qv4.w*qv4.w;
        float sk = kv4.x*kv4.x + kv4.y*kv4.y + kv4.z*kv4.z + kv4.w*kv4.w;
#pragma unroll
        for (int off = 16; off > 0; off >>= 1) {
            sq += __shfl_xor_sync(0xffffffffu, sq, off);
            sk += __shfl_xor_sync(0xffffffffu, sk, off);
        }
        float fq = 1.0f / fmaxf(sqrtf(sq), eps_n);
        float fk = 1.0f / fmaxf(sqrtf(sk), eps_n);
        qv4.x *= fq; qv4.y *= fq; qv4.z *= fq; qv4.w *= fq;
        kv4.x *= fk; kv4.y *= fk; kv4.z *= fk; kv4.w *= fk;

        qT[(c4+0)*QK_PAD + row] = qv4.x; qT[(c4+1)*QK_PAD + row] = qv4.y;
        qT[(c4+2)*QK_PAD + row] = qv4.z; qT[(c4+3)*QK_PAD + row] = qv4.w;
        kT[(c4+0)*QK_PAD + row] = kv4.x; kT[(c4+1)*QK_PAD + row] = kv4.y;
        kT[(c4+2)*QK_PAD + row] = kv4.z; kT[(c4+3)*QK_PAD + row] = kv4.w;
    }
    __syncthreads();

    // phase 2: S[i][j] = qn_i . kn_j, masked to tril
    {
        const int tx = tid & 15, ty = tid >> 4;
        const int j0 = tx * 4, i0 = ty * 4;
        float acc[4][4] = {};
#pragma unroll 8
        for (int kk = 0; kk < 128; kk++) {
            float4 a = *(const float4*)&qT[kk * QK_PAD + i0];
            float4 bb4 = *(const float4*)&kT[kk * QK_PAD + j0];
            const float am[4] = {a.x, a.y, a.z, a.w};
            const float bm[4] = {bb4.x, bb4.y, bb4.z, bb4.w};
#pragma unroll
            for (int m = 0; m < 4; m++)
#pragma unroll
                for (int n = 0; n < 4; n++)
                    acc[m][n] += am[m] * bm[n];
        }
#pragma unroll
        for (int m = 0; m < 4; m++) {
            int i = i0 + m;
            float4 w;
            w.x = (j0 + 0 <= i) ? acc[m][0] : 0.0f;
            w.y = (j0 + 1 <= i) ? acc[m][1] : 0.0f;
            w.z = (j0 + 2 <= i) ? acc[m][2] : 0.0f;
            w.w = (j0 + 3 <= i) ? acc[m][3] : 0.0f;
            *(float4*)&S[i * 64 + j0] = w;
        }
    }
    __syncthreads();

    // load gv = softplus(beta)*v into the qT region
    for (int f = tid; f < 64 * 32; f += 256) {
        int row = f >> 5;
        int c4  = (f & 31) << 2;
        float bta = beta[(tok0 + row) * NHEADS + h];
        float sp  = (bta > 20.0f) ? bta : log1pf(expf(bta));
        float4 vv = *(const float4*)(v + base + (size_t)row * tokstride + c4);
        vv.x *= sp; vv.y *= sp; vv.z *= sp; vv.w *= sp;
        *(float4*)&gvS[row * 128 + c4] = vv;
    }
    __syncthreads();

    // phase 3: O[i][:] = sum_{j<=i} S[i][j] * gv[j][:]
    {
        const int tx = tid & 15, ty = tid >> 4;
        const int kk0 = tx * 8, i0 = ty * 4;
        float o[4][8] = {};
        const int jend = i0 + 4;
        for (int j = 0; j < jend; j++) {
            float s0 = S[(i0+0)*64 + j];
            float s1 = S[(i0+1)*64 + j];
            float s2 = S[(i0+2)*64 + j];
            float s3 = S[(i0+3)*64 + j];
            float4 g0 = *(const float4*)&gvS[j * 128 + kk0];
            float4 g1 = *(const float4*)&gvS[j * 128 + kk0 + 4];
            const float gg[8] = {g0.x,g0.y,g0.z,g0.w,g1.x,g1.y,g1.z,g1.w};
#pragma unroll
            for (int n = 0; n < 8; n++) {
                o[0][n] += s0 * gg[n];
                o[1][n] += s1 * gg[n];
                o[2][n] += s2 * gg[n];
                o[3][n] += s3 * gg[n];
            }
        }
#pragma unroll
        for (int m = 0; m < 4; m++) {
            float* op = out + base + (size_t)(i0 + m) * tokstride + kk0;
            *(float4*)(op)     = make_float4(o[m][0], o[m][1], o[m][2], o[m][3]);
            *(float4*)(op + 4) = make_float4(o[m][4], o[m][5], o[m][6], o[m][7]);
        }
    }
}

// ---------------------------------------------------------------------------
extern "C" void kernel_launch(void* const* d_in, const int* in_sizes, int n_in,
                              void* d_out, int out_size)
{
    const float* hs   = (const float*)d_in[0];
    const float* q_w  = (const float*)d_in[1];
    const float* q_b  = (const float*)d_in[2];
    const float* k_w  = (const float*)d_in[3];
    const float* k_b  = (const float*)d_in[4];
    const float* v_w  = (const float*)d_in[5];
    const float* v_b  = (const float*)d_in[6];
    /* a_w, a_b (d_in[7], d_in[8]) are dead code in the reference */
    const float* b_w  = (const float*)d_in[9];
    const float* b_b  = (const float*)d_in[10];
    const float* og_w = (const float*)d_in[11];
    const float* o_w  = (const float*)d_in[12];
    const float* o_b  = (const float*)d_in[13];
    float* out = (float*)d_out;

    float *gq, *gk, *gv, *gog, *gao, *gbeta;
    __nv_bfloat16 *ga1, *gwb;
    cudaGetSymbolAddress((void**)&gq,    g_q);
    cudaGetSymbolAddress((void**)&gk,    g_k);
    cudaGetSymbolAddress((void**)&gv,    g_v);
    cudaGetSymbolAddress((void**)&gog,   g_og);
    cudaGetSymbolAddress((void**)&gao,   g_ao);
    cudaGetSymbolAddress((void**)&gbeta, g_beta);
    cudaGetSymbolAddress((void**)&ga1,   g_a1);
    cudaGetSymbolAddress((void**)&gwb,   g_wb);

    cudaFuncSetAttribute(gemm_bf16,
                         cudaFuncAttributeMaxDynamicSharedMemorySize, GSMEM);

    const dim3 gG(QKV / 128, MROWS / 256);        // (16, 64)
    const unsigned actBlocks = (unsigned)((size_t)MROWS * 512 / 256);  // 32768
    const unsigned wBlocks   = (unsigned)((size_t)QKV  * 512 / 256);   // 4096

    // split activations once [hi|lo]
    split2<<<actBlocks, 256>>>(hs, ga1);

    // q,k,v,og projections
    split2<<<wBlocks, 256>>>(q_w, gwb);
    gemm_bf16<<<gG, 512, GSMEM>>>(ga1, gwb, q_b, gq);
    split2<<<wBlocks, 256>>>(k_w, gwb);
    gemm_bf16<<<gG, 512, GSMEM>>>(ga1, gwb, k_b, gk);
    split2<<<wBlocks, 256>>>(v_w, gwb);
    gemm_bf16<<<gG, 512, GSMEM>>>(ga1, gwb, v_b, gv);
    split2<<<wBlocks, 256>>>(og_w, gwb);
    gemm_bf16<<<gG, 512, GSMEM>>>(ga1, gwb, nullptr, gog);

    beta_gemm<<<MROWS / 8, 256>>>(hs, b_w, b_b, gbeta);

    size_t smemA = (size_t)(2 * 128 * QK_PAD + 64 * 64) * sizeof(float);
    cudaFuncSetAttribute(attn_kernel,
                         cudaFuncAttributeMaxDynamicSharedMemorySize, (int)smemA);
    dim3 gAttn(NHEADS, SEQ / CHUNK, BATCH);
    attn_kernel<<<gAttn, 256, smemA>>>(gq, gk, gv, gbeta, gao);

    // gate + split gated activations (reuses ga1), then output projection
    gate_split<<<actBlocks, 256>>>(gao, gog, ga1);
    split2<<<wBlocks, 256>>>(o_w, gwb);
    gemm_bf16<<<gG, 512, GSMEM>>>(ga1, gwb, o_b, out);
}

// round 9
// speedup vs baseline: 7.3934x; 1.3434x over previous
#include <cuda_runtime.h>
#include <cuda_fp16.h>
#include <math.h>
#include <stdint.h>

#define NHEADS 16
#define HDIM   128
#define CHUNK  64
#define BATCH  4
#define SEQ    4096
#define HID    2048
#define MROWS  (BATCH*SEQ)            /* 16384 */
#define QKV    (NHEADS*HDIM)          /* 2048  */
#define KW2    (2*HID)                /* 4096: weight [hi | lo] */

// ---------------- scratch (device globals; no allocation allowed) -----------
static __device__ float g_q  [(size_t)MROWS*QKV];
static __device__ float g_k  [(size_t)MROWS*QKV];
static __device__ float g_v  [(size_t)MROWS*QKV];
static __device__ float g_og [(size_t)MROWS*QKV];
static __device__ float g_ao [(size_t)MROWS*QKV];
static __device__ float g_beta[(size_t)MROWS*NHEADS];
static __device__ __half g_a1 [(size_t)MROWS*HID];     // fp16 activations (hi)
static __device__ __half g_wq [(size_t)QKV*KW2];
static __device__ __half g_wk [(size_t)QKV*KW2];
static __device__ __half g_wv [(size_t)QKV*KW2];
static __device__ __half g_wog[(size_t)QKV*KW2];
static __device__ __half g_wo [(size_t)QKV*KW2];

// ---------------- PTX helpers (family-PTX-safe: sm_80-era only) -------------
__device__ __forceinline__ uint32_t smem_u32(const void* p) {
    uint32_t a;
    asm("{ .reg .u64 t; cvta.to.shared.u64 t, %1; cvt.u32.u64 %0, t; }"
        : "=r"(a) : "l"(p));
    return a;
}
__device__ __forceinline__ void cpa16(uint32_t d, const void* s) {
    asm volatile("cp.async.cg.shared.global [%0], [%1], 16;" :: "r"(d), "l"(s));
}
__device__ __forceinline__ void cp_commit() {
    asm volatile("cp.async.commit_group;" ::: "memory");
}
__device__ __forceinline__ void cp_wait2() {
    asm volatile("cp.async.wait_group 2;" ::: "memory");
}
__device__ __forceinline__ void ldsm4(uint32_t& r0, uint32_t& r1,
                                      uint32_t& r2, uint32_t& r3, uint32_t a) {
    asm volatile("ldmatrix.sync.aligned.m8n8.x4.shared.b16 {%0,%1,%2,%3}, [%4];"
                 : "=r"(r0), "=r"(r1), "=r"(r2), "=r"(r3) : "r"(a));
}
__device__ __forceinline__ void mma16816(float* c, const uint32_t* a,
                                         uint32_t b0, uint32_t b1) {
    asm volatile(
        "mma.sync.aligned.m16n8k16.row.col.f32.f16.f16.f32 "
        "{%0,%1,%2,%3}, {%4,%5,%6,%7}, {%8,%9}, {%0,%1,%2,%3};"
        : "+f"(c[0]), "+f"(c[1]), "+f"(c[2]), "+f"(c[3])
        : "r"(a[0]), "r"(a[1]), "r"(a[2]), "r"(a[3]), "r"(b0), "r"(b1));
}

// ---------------------------------------------------------------------------
// mma.sync fp16 GEMM, 2-product hi/lo split on weights only:
//   C = Ahi*Whi^T + Ahi*Wlo^T  (+bias)
// A: fp16 [M, 2048] (hi only). W: fp16 [2048, 4096] = [hi | lo].
// CTA tile 256x128, 512 threads (16 warps, warp tile 64x32).
// 32 super-chunks of 64 k-cols; stage = A 32KB + Whi 16KB + Wlo 16KB = 64KB;
// 3-stage cp.async pipeline (192KB smem).
// ---------------------------------------------------------------------------
#define NSC       32
#define OFF_A     0
#define OFF_WHI   32768
#define OFF_WLO   49152
#define STG_BYTES 65536
#define GSMEM     (3*STG_BYTES)          /* 196608 */

__global__ __launch_bounds__(512, 1)
void gemm_f16(const __half* __restrict__ A, const __half* __restrict__ W,
              const float* __restrict__ bias, float* __restrict__ C)
{
    extern __shared__ __align__(1024) char smem[];
    const uint32_t sb = smem_u32(smem);
    const int tid = threadIdx.x;
    const int bn0 = blockIdx.x * 128;
    const int bm0 = blockIdx.y * 256;

    // ---- loader geometry ----
    const int r0  = tid >> 3;            // 0..63
    const int c16 = (tid & 7) * 16;      // byte offset within 128B chunk-row
    const size_t rowA = (size_t)HID * 2; // 4096 B
    const size_t rowW = (size_t)KW2 * 2; // 8192 B

    const char* abase = (const char*)A + (size_t)bm0 * rowA + c16;
    const char* wbase = (const char*)W + (size_t)bn0 * rowW + c16;

    auto load_stage = [&](int sc, int s) {
        const uint32_t st = sb + s * STG_BYTES;
        const char* ap = abase + (size_t)sc * 128;
        const char* wp = wbase + (size_t)sc * 128;
#pragma unroll
        for (int i = 0; i < 4; i++) {
            const int row = r0 + i * 64;
            uint32_t off = (uint32_t)row * 128 + (uint32_t)c16;
            uint32_t sw  = off ^ ((off >> 3) & 0x70);
            cpa16(st + OFF_A + sw, ap + (size_t)row * rowA);
        }
#pragma unroll
        for (int i = 0; i < 2; i++) {
            const int row = r0 + i * 64;
            uint32_t off = (uint32_t)row * 128 + (uint32_t)c16;
            uint32_t sw  = off ^ ((off >> 3) & 0x70);
            const char* g = wp + (size_t)row * rowW;
            cpa16(st + OFF_WHI + sw, g);
            cpa16(st + OFF_WLO + sw, g + 4096);   // lo segment: +2048 fp16
        }
        cp_commit();
    };

    // ---- warp fragment geometry ----
    const int lane = tid & 31;
    const int warp = tid >> 5;
    const int wm = warp >> 2;            // 0..3  -> 64-row block
    const int wn = warp & 3;             // 0..3  -> 32-col block

    const int a_row  = wm * 64 + (lane & 15);
    const int a_sel  = (lane >> 4) * 16;
    const uint32_t a_x = (uint32_t)((a_row & 7) << 4);
    const int b_row  = wn * 32 + ((lane >> 4) << 3) + (lane & 7);
    const int b_sel  = ((lane >> 3) & 1) * 16;
    const uint32_t b_x = (uint32_t)((b_row & 7) << 4);

    float acc[4][4][4];
#pragma unroll
    for (int i = 0; i < 4; i++)
#pragma unroll
        for (int j = 0; j < 4; j++)
#pragma unroll
            for (int r = 0; r < 4; r++) acc[i][j][r] = 0.0f;

    // prologue
    load_stage(0, 0);
    load_stage(1, 1);
    load_stage(2, 2);

    for (int sc = 0; sc < NSC; sc++) {
        const int s = sc % 3;
        cp_wait2();
        __syncthreads();

        const uint32_t st = sb + s * STG_BYTES;

#pragma unroll
        for (int ks = 0; ks < 4; ks++) {
            const uint32_t kb = (uint32_t)(ks * 32);
            uint32_t bhi[2][4], blo[2][4];
#pragma unroll
            for (int nb = 0; nb < 2; nb++) {
                uint32_t broff = (uint32_t)(b_row + nb * 16) * 128
                               + ((kb + (uint32_t)b_sel) ^ b_x);
                ldsm4(bhi[nb][0], bhi[nb][1], bhi[nb][2], bhi[nb][3],
                      st + OFF_WHI + broff);
                ldsm4(blo[nb][0], blo[nb][1], blo[nb][2], blo[nb][3],
                      st + OFF_WLO + broff);
            }
#pragma unroll
            for (int mf = 0; mf < 4; mf++) {
                uint32_t aroff = (uint32_t)(a_row + mf * 16) * 128
                               + ((kb + (uint32_t)a_sel) ^ a_x);
                uint32_t a[4];
                ldsm4(a[0], a[1], a[2], a[3], st + OFF_A + aroff);
                mma16816(acc[mf][0], a, bhi[0][0], bhi[0][1]);
                mma16816(acc[mf][1], a, bhi[0][2], bhi[0][3]);
                mma16816(acc[mf][2], a, bhi[1][0], bhi[1][1]);
                mma16816(acc[mf][3], a, bhi[1][2], bhi[1][3]);
                mma16816(acc[mf][0], a, blo[0][0], blo[0][1]);
                mma16816(acc[mf][1], a, blo[0][2], blo[0][3]);
                mma16816(acc[mf][2], a, blo[1][0], blo[1][1]);
                mma16816(acc[mf][3], a, blo[1][2], blo[1][3]);
            }
        }
        __syncthreads();

        if (sc + 3 < NSC) {
            load_stage(sc + 3, s);
        } else {
            cp_commit();   // keep group count uniform for cp_wait2
        }
    }

    // ---- epilogue ----
#pragma unroll
    for (int nf = 0; nf < 4; nf++) {
        const int col = bn0 + wn * 32 + nf * 8 + (lane & 3) * 2;
        float b0 = 0.0f, b1 = 0.0f;
        if (bias) { b0 = bias[col]; b1 = bias[col + 1]; }
#pragma unroll
        for (int mf = 0; mf < 4; mf++) {
            const int row = bm0 + wm * 64 + mf * 16 + (lane >> 2);
            float2 v0 = make_float2(acc[mf][nf][0] + b0, acc[mf][nf][1] + b1);
            float2 v1 = make_float2(acc[mf][nf][2] + b0, acc[mf][nf][3] + b1);
            *(float2*)(C + (size_t)row * QKV + col)       = v0;
            *(float2*)(C + (size_t)(row + 8) * QKV + col) = v1;
        }
    }
}

// ---------------------------------------------------------------------------
// fp32 -> fp16 helpers
// ---------------------------------------------------------------------------
__device__ __forceinline__ uint2 pack4h(float x, float y, float z, float w) {
    __half2 a = __floats2half2_rn(x, y);
    __half2 b = __floats2half2_rn(z, w);
    uint2 r;
    r.x = *(uint32_t*)&a;
    r.y = *(uint32_t*)&b;
    return r;
}

// activations: straight fp32 -> fp16 (hi only)
__global__ __launch_bounds__(256)
void cvt_half(const float* __restrict__ in, __half* __restrict__ out)
{
    size_t i = ((size_t)blockIdx.x * 256 + threadIdx.x) * 4;
    float4 v = *(const float4*)(in + i);
    *(uint2*)(out + i) = pack4h(v.x, v.y, v.z, v.w);
}

// weights: fp32 [2048,2048] -> fp16 [2048, 4096] = [hi | lo]
__global__ __launch_bounds__(256)
void wsplit(const float* __restrict__ in, __half* __restrict__ out)
{
    size_t idx = (size_t)blockIdx.x * 256 + threadIdx.x;
    size_t row = idx >> 9;
    int c4 = (int)(idx & 511) << 2;
    float4 v = *(const float4*)(in + row * HID + c4);
    __half h0 = __float2half_rn(v.x), h1 = __float2half_rn(v.y);
    __half h2 = __float2half_rn(v.z), h3 = __float2half_rn(v.w);
    float l0 = v.x - __half2float(h0), l1 = v.y - __half2float(h1);
    float l2 = v.z - __half2float(h2), l3 = v.w - __half2float(h3);
    __half2 hA = __halves2half2(h0, h1), hB = __halves2half2(h2, h3);
    uint2 hi; hi.x = *(uint32_t*)&hA; hi.y = *(uint32_t*)&hB;
    __half* o = out + row * KW2 + c4;
    *(uint2*)o = hi;
    *(uint2*)(o + HID) = pack4h(l0, l1, l2, l3);
}

// gated = ao * silu(og) -> fp16 activations (hi only)
__global__ __launch_bounds__(256)
void gate_half(const float* __restrict__ ao, const float* __restrict__ og,
               __half* __restrict__ out)
{
    size_t i = ((size_t)blockIdx.x * 256 + threadIdx.x) * 4;
    float4 a = *(const float4*)(ao + i);
    float4 g = *(const float4*)(og + i);
    float yx = a.x * (g.x / (1.0f + expf(-g.x)));
    float yy = a.y * (g.y / (1.0f + expf(-g.y)));
    float yz = a.z * (g.z / (1.0f + expf(-g.z)));
    float yw = a.w * (g.w / (1.0f + expf(-g.w)));
    *(uint2*)(out + i) = pack4h(yx, yy, yz, yw);
}

// ---------------------------------------------------------------------------
// beta = hs @ b_w^T + b_b  (N=16), fp32
// ---------------------------------------------------------------------------
__global__ __launch_bounds__(256)
void beta_gemm(const float* __restrict__ hs, const float* __restrict__ bw,
               const float* __restrict__ bb, float* __restrict__ beta)
{
    int warp = (blockIdx.x * blockDim.x + threadIdx.x) >> 5;
    int lane = threadIdx.x & 31;
    if (warp >= MROWS) return;
    const float* x = hs + (size_t)warp * HID;

    float acc[NHEADS];
#pragma unroll
    for (int j = 0; j < NHEADS; j++) acc[j] = 0.0f;

    for (int t = 0; t < HID / 128; t++) {
        int k = t * 128 + lane * 4;
        float4 xv = *(const float4*)(x + k);
#pragma unroll
        for (int j = 0; j < NHEADS; j++) {
            float4 wv = *(const float4*)(bw + (size_t)j * HID + k);
            acc[j] += xv.x*wv.x + xv.y*wv.y + xv.z*wv.z + xv.w*wv.w;
        }
    }
#pragma unroll
    for (int j = 0; j < NHEADS; j++)
#pragma unroll
        for (int off = 16; off > 0; off >>= 1)
            acc[j] += __shfl_xor_sync(0xffffffffu, acc[j], off);

    if (lane < NHEADS) {
        float v = 0.0f;
#pragma unroll
        for (int j = 0; j < NHEADS; j++) if (lane == j) v = acc[j];
        beta[(size_t)warp * NHEADS + lane] = v + bb[lane];
    }
}

// ---------------------------------------------------------------------------
// Chunk attention with fused pointwise (l2norm on q,k; softplus(beta)*v).
// S = tril(Qc Kc^T) (decay == 1 on kept region); O = S @ GVc.
// ---------------------------------------------------------------------------
#define QK_PAD 68
__global__ __launch_bounds__(256)
void attn_kernel(const float* __restrict__ q, const float* __restrict__ k,
                 const float* __restrict__ v, const float* __restrict__ beta,
                 float* __restrict__ out)
{
    extern __shared__ float sm[];
    float* qT  = sm;
    float* kT  = qT + 128 * QK_PAD;
    float* S   = kT + 128 * QK_PAD;
    float* gvS = qT;

    const int h  = blockIdx.x;
    const int cn = blockIdx.y;
    const int b  = blockIdx.z;
    const int tid = threadIdx.x;

    const size_t tok0 = (size_t)b * SEQ + (size_t)cn * CHUNK;
    const size_t base = (tok0 * NHEADS + h) * HDIM;
    const int tokstride = NHEADS * HDIM;
    const float eps_n = 1.1313708499e-11f;   // sqrt(128) * 1e-12

    for (int f = tid; f < 64 * 32; f += 256) {
        int row = f >> 5;
        int c4  = (f & 31) << 2;
        size_t g = base + (size_t)row * tokstride + c4;
        float4 qv4 = *(const float4*)(q + g);
        float4 kv4 = *(const float4*)(k + g);

        float sq = qv4.x*qv4.x + qv4.y*qv4.y + qv4.z*qv4.z + qv4.w*qv4.w;
        float sk = kv4.x*kv4.x + kv4.y*kv4.y + kv4.z*kv4.z + kv4.w*kv4.w;
#pragma unroll
        for (int off = 16; off > 0; off >>= 1) {
            sq += __shfl_xor_sync(0xffffffffu, sq, off);
            sk += __shfl_xor_sync(0xffffffffu, sk, off);
        }
        float fq = 1.0f / fmaxf(sqrtf(sq), eps_n);
        float fk = 1.0f / fmaxf(sqrtf(sk), eps_n);
        qv4.x *= fq; qv4.y *= fq; qv4.z *= fq; qv4.w *= fq;
        kv4.x *= fk; kv4.y *= fk; kv4.z *= fk; kv4.w *= fk;

        qT[(c4+0)*QK_PAD + row] = qv4.x; qT[(c4+1)*QK_PAD + row] = qv4.y;
        qT[(c4+2)*QK_PAD + row] = qv4.z; qT[(c4+3)*QK_PAD + row] = qv4.w;
        kT[(c4+0)*QK_PAD + row] = kv4.x; kT[(c4+1)*QK_PAD + row] = kv4.y;
        kT[(c4+2)*QK_PAD + row] = kv4.z; kT[(c4+3)*QK_PAD + row] = kv4.w;
    }
    __syncthreads();

    {
        const int tx = tid & 15, ty = tid >> 4;
        const int j0 = tx * 4, i0 = ty * 4;
        float acc[4][4] = {};
#pragma unroll 8
        for (int kk = 0; kk < 128; kk++) {
            float4 a = *(const float4*)&qT[kk * QK_PAD + i0];
            float4 bb4 = *(const float4*)&kT[kk * QK_PAD + j0];
            const float am[4] = {a.x, a.y, a.z, a.w};
            const float bm[4] = {bb4.x, bb4.y, bb4.z, bb4.w};
#pragma unroll
            for (int m = 0; m < 4; m++)
#pragma unroll
                for (int n = 0; n < 4; n++)
                    acc[m][n] += am[m] * bm[n];
        }
#pragma unroll
        for (int m = 0; m < 4; m++) {
            int i = i0 + m;
            float4 w;
            w.x = (j0 + 0 <= i) ? acc[m][0] : 0.0f;
            w.y = (j0 + 1 <= i) ? acc[m][1] : 0.0f;
            w.z = (j0 + 2 <= i) ? acc[m][2] : 0.0f;
            w.w = (j0 + 3 <= i) ? acc[m][3] : 0.0f;
            *(float4*)&S[i * 64 + j0] = w;
        }
    }
    __syncthreads();

    for (int f = tid; f < 64 * 32; f += 256) {
        int row = f >> 5;
        int c4  = (f & 31) << 2;
        float bta = beta[(tok0 + row) * NHEADS + h];
        float sp  = (bta > 20.0f) ? bta : log1pf(expf(bta));
        float4 vv = *(const float4*)(v + base + (size_t)row * tokstride + c4);
        vv.x *= sp; vv.y *= sp; vv.z *= sp; vv.w *= sp;
        *(float4*)&gvS[row * 128 + c4] = vv;
    }
    __syncthreads();

    {
        const int tx = tid & 15, ty = tid >> 4;
        const int kk0 = tx * 8, i0 = ty * 4;
        float o[4][8] = {};
        const int jend = i0 + 4;
        for (int j = 0; j < jend; j++) {
            float s0 = S[(i0+0)*64 + j];
            float s1 = S[(i0+1)*64 + j];
            float s2 = S[(i0+2)*64 + j];
            float s3 = S[(i0+3)*64 + j];
            float4 g0 = *(const float4*)&gvS[j * 128 + kk0];
            float4 g1 = *(const float4*)&gvS[j * 128 + kk0 + 4];
            const float gg[8] = {g0.x,g0.y,g0.z,g0.w,g1.x,g1.y,g1.z,g1.w};
#pragma unroll
            for (int n = 0; n < 8; n++) {
                o[0][n] += s0 * gg[n];
                o[1][n] += s1 * gg[n];
                o[2][n] += s2 * gg[n];
                o[3][n] += s3 * gg[n];
            }
        }
#pragma unroll
        for (int m = 0; m < 4; m++) {
            float* op = out + base + (size_t)(i0 + m) * tokstride + kk0;
            *(float4*)(op)     = make_float4(o[m][0], o[m][1], o[m][2], o[m][3]);
            *(float4*)(op + 4) = make_float4(o[m][4], o[m][5], o[m][6], o[m][7]);
        }
    }
}

// ---------------------------------------------------------------------------
extern "C" void kernel_launch(void* const* d_in, const int* in_sizes, int n_in,
                              void* d_out, int out_size)
{
    const float* hs   = (const float*)d_in[0];
    const float* q_w  = (const float*)d_in[1];
    const float* q_b  = (const float*)d_in[2];
    const float* k_w  = (const float*)d_in[3];
    const float* k_b  = (const float*)d_in[4];
    const float* v_w  = (const float*)d_in[5];
    const float* v_b  = (const float*)d_in[6];
    /* a_w, a_b (d_in[7], d_in[8]) are dead code in the reference */
    const float* b_w  = (const float*)d_in[9];
    const float* b_b  = (const float*)d_in[10];
    const float* og_w = (const float*)d_in[11];
    const float* o_w  = (const float*)d_in[12];
    const float* o_b  = (const float*)d_in[13];
    float* out = (float*)d_out;

    float *gq, *gk, *gv, *gog, *gao, *gbeta;
    __half *ga1, *gwq, *gwk, *gwv, *gwog, *gwo;
    cudaGetSymbolAddress((void**)&gq,    g_q);
    cudaGetSymbolAddress((void**)&gk,    g_k);
    cudaGetSymbolAddress((void**)&gv,    g_v);
    cudaGetSymbolAddress((void**)&gog,   g_og);
    cudaGetSymbolAddress((void**)&gao,   g_ao);
    cudaGetSymbolAddress((void**)&gbeta, g_beta);
    cudaGetSymbolAddress((void**)&ga1,   g_a1);
    cudaGetSymbolAddress((void**)&gwq,   g_wq);
    cudaGetSymbolAddress((void**)&gwk,   g_wk);
    cudaGetSymbolAddress((void**)&gwv,   g_wv);
    cudaGetSymbolAddress((void**)&gwog,  g_wog);
    cudaGetSymbolAddress((void**)&gwo,   g_wo);

    cudaFuncSetAttribute(gemm_f16,
                         cudaFuncAttributeMaxDynamicSharedMemorySize, GSMEM);

    const dim3 gG(QKV / 128, MROWS / 256);        // (16, 64)
    const unsigned actBlocks = (unsigned)((size_t)MROWS * HID / 4 / 256);  // 32768
    const unsigned wBlocks   = (unsigned)((size_t)QKV  * HID / 4 / 256);   // 4096

    // launches 0-4: activation convert + 4 weight splits
    cvt_half<<<actBlocks, 256>>>(hs, ga1);
    wsplit<<<wBlocks, 256>>>(q_w,  gwq);
    wsplit<<<wBlocks, 256>>>(k_w,  gwk);
    wsplit<<<wBlocks, 256>>>(v_w,  gwv);
    wsplit<<<wBlocks, 256>>>(og_w, gwog);

    // launch 5 (ncu -s 5 -c 1 profiles this one): first projection GEMM
    gemm_f16<<<gG, 512, GSMEM>>>(ga1, gwq,  q_b,    gq);
    gemm_f16<<<gG, 512, GSMEM>>>(ga1, gwk,  k_b,    gk);
    gemm_f16<<<gG, 512, GSMEM>>>(ga1, gwv,  v_b,    gv);
    gemm_f16<<<gG, 512, GSMEM>>>(ga1, gwog, nullptr, gog);

    beta_gemm<<<MROWS / 8, 256>>>(hs, b_w, b_b, gbeta);

    size_t smemA = (size_t)(2 * 128 * QK_PAD + 64 * 64) * sizeof(float);
    cudaFuncSetAttribute(attn_kernel,
                         cudaFuncAttributeMaxDynamicSharedMemorySize, (int)smemA);
    dim3 gAttn(NHEADS, SEQ / CHUNK, BATCH);
    attn_kernel<<<gAttn, 256, smemA>>>(gq, gk, gv, gbeta, gao);

    // gate into fp16 activations (reuses ga1), then output projection
    gate_half<<<actBlocks, 256>>>(gao, gog, ga1);
    wsplit<<<wBlocks, 256>>>(o_w, gwo);
    gemm_f16<<<gG, 512, GSMEM>>>(ga1, gwo, o_b, out);
}

// round 10
// speedup vs baseline: 11.4954x; 1.5548x over previous
#include <cuda_runtime.h>
#include <cuda_fp16.h>
#include <math.h>
#include <stdint.h>

#define NHEADS 16
#define HDIM   128
#define CHUNK  64
#define BATCH  4
#define SEQ    4096
#define HID    2048
#define MROWS  (BATCH*SEQ)            /* 16384 */
#define QKV    (NHEADS*HDIM)          /* 2048  */

// ---------------- scratch (device globals; no allocation allowed) -----------
static __device__ float g_q  [(size_t)MROWS*QKV];
static __device__ float g_k  [(size_t)MROWS*QKV];
static __device__ float g_v  [(size_t)MROWS*QKV];
static __device__ float g_og [(size_t)MROWS*QKV];
static __device__ float g_ao [(size_t)MROWS*QKV];
static __device__ float g_beta[(size_t)MROWS*NHEADS];
static __device__ __half g_a1 [(size_t)MROWS*HID];     // fp16 activations
static __device__ __half g_wq [(size_t)QKV*HID];
static __device__ __half g_wk [(size_t)QKV*HID];
static __device__ __half g_wv [(size_t)QKV*HID];
static __device__ __half g_wog[(size_t)QKV*HID];
static __device__ __half g_wo [(size_t)QKV*HID];

// ---------------- PTX helpers (family-PTX-safe: sm_80-era only) -------------
__device__ __forceinline__ uint32_t smem_u32(const void* p) {
    uint32_t a;
    asm("{ .reg .u64 t; cvta.to.shared.u64 t, %1; cvt.u32.u64 %0, t; }"
        : "=r"(a) : "l"(p));
    return a;
}
__device__ __forceinline__ void cpa16(uint32_t d, const void* s) {
    asm volatile("cp.async.cg.shared.global [%0], [%1], 16;" :: "r"(d), "l"(s));
}
__device__ __forceinline__ void cp_commit() {
    asm volatile("cp.async.commit_group;" ::: "memory");
}
__device__ __forceinline__ void cp_wait3() {
    asm volatile("cp.async.wait_group 3;" ::: "memory");
}
__device__ __forceinline__ void ldsm4(uint32_t& r0, uint32_t& r1,
                                      uint32_t& r2, uint32_t& r3, uint32_t a) {
    asm volatile("ldmatrix.sync.aligned.m8n8.x4.shared.b16 {%0,%1,%2,%3}, [%4];"
                 : "=r"(r0), "=r"(r1), "=r"(r2), "=r"(r3) : "r"(a));
}
__device__ __forceinline__ void mma16816(float* c, const uint32_t* a,
                                         uint32_t b0, uint32_t b1) {
    asm volatile(
        "mma.sync.aligned.m16n8k16.row.col.f32.f16.f16.f32 "
        "{%0,%1,%2,%3}, {%4,%5,%6,%7}, {%8,%9}, {%0,%1,%2,%3};"
        : "+f"(c[0]), "+f"(c[1]), "+f"(c[2]), "+f"(c[3])
        : "r"(a[0]), "r"(a[1]), "r"(a[2]), "r"(a[3]), "r"(b0), "r"(b1));
}

// ---------------------------------------------------------------------------
// mma.sync fp16 GEMM: C[M,2048] = A[M,2048] @ W[2048,2048]^T (+bias), fp32 out
// CTA tile 256x128, 512 threads (16 warps, warp tile 64x32).
// 32 chunks of 64 k-cols; stage = A 32KB + W 16KB = 48KB; 4-stage cp.async.
// ---------------------------------------------------------------------------
#define NSC       32
#define OFF_A     0
#define OFF_W     32768
#define STG_BYTES 49152
#define GSMEM     (4*STG_BYTES)          /* 196608 */

__global__ __launch_bounds__(512, 1)
void gemm_f16(const __half* __restrict__ A, const __half* __restrict__ W,
              const float* __restrict__ bias, float* __restrict__ C)
{
    extern __shared__ __align__(1024) char smem[];
    const uint32_t sb = smem_u32(smem);
    const int tid = threadIdx.x;
    const int bn0 = blockIdx.x * 128;
    const int bm0 = blockIdx.y * 256;

    // ---- loader geometry ----
    const int r0  = tid >> 3;            // 0..63
    const int c16 = (tid & 7) * 16;      // byte offset within 128B chunk-row
    const size_t rowHB = (size_t)HID * 2; // 4096 B row stride (A and W)

    const char* abase = (const char*)A + (size_t)bm0 * rowHB + c16;
    const char* wbase = (const char*)W + (size_t)bn0 * rowHB + c16;

    auto load_stage = [&](int sc, int s) {
        const uint32_t st = sb + s * STG_BYTES;
        const char* ap = abase + (size_t)sc * 128;
        const char* wp = wbase + (size_t)sc * 128;
#pragma unroll
        for (int i = 0; i < 4; i++) {
            const int row = r0 + i * 64;
            uint32_t off = (uint32_t)row * 128 + (uint32_t)c16;
            uint32_t sw  = off ^ ((off >> 3) & 0x70);
            cpa16(st + OFF_A + sw, ap + (size_t)row * rowHB);
        }
#pragma unroll
        for (int i = 0; i < 2; i++) {
            const int row = r0 + i * 64;
            uint32_t off = (uint32_t)row * 128 + (uint32_t)c16;
            uint32_t sw  = off ^ ((off >> 3) & 0x70);
            cpa16(st + OFF_W + sw, wp + (size_t)row * rowHB);
        }
        cp_commit();
    };

    // ---- warp fragment geometry ----
    const int lane = tid & 31;
    const int warp = tid >> 5;
    const int wm = warp >> 2;            // 0..3  -> 64-row block
    const int wn = warp & 3;             // 0..3  -> 32-col block

    const int a_row  = wm * 64 + (lane & 15);
    const int a_sel  = (lane >> 4) * 16;
    const uint32_t a_x = (uint32_t)((a_row & 7) << 4);
    const int b_row  = wn * 32 + ((lane >> 4) << 3) + (lane & 7);
    const int b_sel  = ((lane >> 3) & 1) * 16;
    const uint32_t b_x = (uint32_t)((b_row & 7) << 4);

    float acc[4][4][4];
#pragma unroll
    for (int i = 0; i < 4; i++)
#pragma unroll
        for (int j = 0; j < 4; j++)
#pragma unroll
            for (int r = 0; r < 4; r++) acc[i][j][r] = 0.0f;

    // prologue: fill 4 stages
    load_stage(0, 0);
    load_stage(1, 1);
    load_stage(2, 2);
    load_stage(3, 3);

    for (int sc = 0; sc < NSC; sc++) {
        const int s = sc & 3;
        cp_wait3();
        __syncthreads();

        const uint32_t st = sb + s * STG_BYTES;

#pragma unroll
        for (int ks = 0; ks < 4; ks++) {
            const uint32_t kb = (uint32_t)(ks * 32);
            uint32_t b[2][4];
#pragma unroll
            for (int nb = 0; nb < 2; nb++) {
                uint32_t broff = (uint32_t)(b_row + nb * 16) * 128
                               + ((kb + (uint32_t)b_sel) ^ b_x);
                ldsm4(b[nb][0], b[nb][1], b[nb][2], b[nb][3], st + OFF_W + broff);
            }
#pragma unroll
            for (int mf = 0; mf < 4; mf++) {
                uint32_t aroff = (uint32_t)(a_row + mf * 16) * 128
                               + ((kb + (uint32_t)a_sel) ^ a_x);
                uint32_t a[4];
                ldsm4(a[0], a[1], a[2], a[3], st + OFF_A + aroff);
                mma16816(acc[mf][0], a, b[0][0], b[0][1]);
                mma16816(acc[mf][1], a, b[0][2], b[0][3]);
                mma16816(acc[mf][2], a, b[1][0], b[1][1]);
                mma16816(acc[mf][3], a, b[1][2], b[1][3]);
            }
        }
        __syncthreads();

        if (sc + 4 < NSC) {
            load_stage(sc + 4, s);
        } else {
            cp_commit();   // keep group count uniform for cp_wait3
        }
    }

    // ---- epilogue ----
#pragma unroll
    for (int nf = 0; nf < 4; nf++) {
        const int col = bn0 + wn * 32 + nf * 8 + (lane & 3) * 2;
        float b0 = 0.0f, b1 = 0.0f;
        if (bias) { b0 = bias[col]; b1 = bias[col + 1]; }
#pragma unroll
        for (int mf = 0; mf < 4; mf++) {
            const int row = bm0 + wm * 64 + mf * 16 + (lane >> 2);
            float2 v0 = make_float2(acc[mf][nf][0] + b0, acc[mf][nf][1] + b1);
            float2 v1 = make_float2(acc[mf][nf][2] + b0, acc[mf][nf][3] + b1);
            *(float2*)(C + (size_t)row * QKV + col)       = v0;
            *(float2*)(C + (size_t)(row + 8) * QKV + col) = v1;
        }
    }
}

// ---------------------------------------------------------------------------
// fp32 -> fp16 convert (activations and weights)
// ---------------------------------------------------------------------------
__device__ __forceinline__ uint2 pack4h(float x, float y, float z, float w) {
    __half2 a = __floats2half2_rn(x, y);
    __half2 b = __floats2half2_rn(z, w);
    uint2 r;
    r.x = *(uint32_t*)&a;
    r.y = *(uint32_t*)&b;
    return r;
}

__global__ __launch_bounds__(256)
void cvt_half(const float* __restrict__ in, __half* __restrict__ out)
{
    size_t i = ((size_t)blockIdx.x * 256 + threadIdx.x) * 4;
    float4 v = *(const float4*)(in + i);
    *(uint2*)(out + i) = pack4h(v.x, v.y, v.z, v.w);
}

// gated = ao * silu(og) -> fp16 activations
__global__ __launch_bounds__(256)
void gate_half(const float* __restrict__ ao, const float* __restrict__ og,
               __half* __restrict__ out)
{
    size_t i = ((size_t)blockIdx.x * 256 + threadIdx.x) * 4;
    float4 a = *(const float4*)(ao + i);
    float4 g = *(const float4*)(og + i);
    float yx = a.x * (g.x / (1.0f + expf(-g.x)));
    float yy = a.y * (g.y / (1.0f + expf(-g.y)));
    float yz = a.z * (g.z / (1.0f + expf(-g.z)));
    float yw = a.w * (g.w / (1.0f + expf(-g.w)));
    *(uint2*)(out + i) = pack4h(yx, yy, yz, yw);
}

// ---------------------------------------------------------------------------
// beta = hs @ b_w^T + b_b  (N=16), fp32
// ---------------------------------------------------------------------------
__global__ __launch_bounds__(256)
void beta_gemm(const float* __restrict__ hs, const float* __restrict__ bw,
               const float* __restrict__ bb, float* __restrict__ beta)
{
    int warp = (blockIdx.x * blockDim.x + threadIdx.x) >> 5;
    int lane = threadIdx.x & 31;
    if (warp >= MROWS) return;
    const float* x = hs + (size_t)warp * HID;

    float acc[NHEADS];
#pragma unroll
    for (int j = 0; j < NHEADS; j++) acc[j] = 0.0f;

    for (int t = 0; t < HID / 128; t++) {
        int k = t * 128 + lane * 4;
        float4 xv = *(const float4*)(x + k);
#pragma unroll
        for (int j = 0; j < NHEADS; j++) {
            float4 wv = *(const float4*)(bw + (size_t)j * HID + k);
            acc[j] += xv.x*wv.x + xv.y*wv.y + xv.z*wv.z + xv.w*wv.w;
        }
    }
#pragma unroll
    for (int j = 0; j < NHEADS; j++)
#pragma unroll
        for (int off = 16; off > 0; off >>= 1)
            acc[j] += __shfl_xor_sync(0xffffffffu, acc[j], off);

    if (lane < NHEADS) {
        float v = 0.0f;
#pragma unroll
        for (int j = 0; j < NHEADS; j++) if (lane == j) v = acc[j];
        beta[(size_t)warp * NHEADS + lane] = v + bb[lane];
    }
}

// ---------------------------------------------------------------------------
// Chunk attention with fused pointwise (l2norm on q,k; softplus(beta)*v).
// S = tril(Qc Kc^T) (decay == 1 on kept region); O = S @ GVc.
// ---------------------------------------------------------------------------
#define QK_PAD 68
__global__ __launch_bounds__(256)
void attn_kernel(const float* __restrict__ q, const float* __restrict__ k,
                 const float* __restrict__ v, const float* __restrict__ beta,
                 float* __restrict__ out)
{
    extern __shared__ float sm[];
    float* qT  = sm;
    float* kT  = qT + 128 * QK_PAD;
    float* S   = kT + 128 * QK_PAD;
    float* gvS = qT;

    const int h  = blockIdx.x;
    const int cn = blockIdx.y;
    const int b  = blockIdx.z;
    const int tid = threadIdx.x;

    const size_t tok0 = (size_t)b * SEQ + (size_t)cn * CHUNK;
    const size_t base = (tok0 * NHEADS + h) * HDIM;
    const int tokstride = NHEADS * HDIM;
    const float eps_n = 1.1313708499e-11f;   // sqrt(128) * 1e-12

    for (int f = tid; f < 64 * 32; f += 256) {
        int row = f >> 5;
        int c4  = (f & 31) << 2;
        size_t g = base + (size_t)row * tokstride + c4;
        float4 qv4 = *(const float4*)(q + g);
        float4 kv4 = *(const float4*)(k + g);

        float sq = qv4.x*qv4.x + qv4.y*qv4.y + qv4.z*qv4.z + qv4.w*qv4.w;
        float sk = kv4.x*kv4.x + kv4.y*kv4.y + kv4.z*kv4.z + kv4.w*kv4.w;
#pragma unroll
        for (int off = 16; off > 0; off >>= 1) {
            sq += __shfl_xor_sync(0xffffffffu, sq, off);
            sk += __shfl_xor_sync(0xffffffffu, sk, off);
        }
        float fq = 1.0f / fmaxf(sqrtf(sq), eps_n);
        float fk = 1.0f / fmaxf(sqrtf(sk), eps_n);
        qv4.x *= fq; qv4.y *= fq; qv4.z *= fq; qv4.w *= fq;
        kv4.x *= fk; kv4.y *= fk; kv4.z *= fk; kv4.w *= fk;

        qT[(c4+0)*QK_PAD + row] = qv4.x; qT[(c4+1)*QK_PAD + row] = qv4.y;
        qT[(c4+2)*QK_PAD + row] = qv4.z; qT[(c4+3)*QK_PAD + row] = qv4.w;
        kT[(c4+0)*QK_PAD + row] = kv4.x; kT[(c4+1)*QK_PAD + row] = kv4.y;
        kT[(c4+2)*QK_PAD + row] = kv4.z; kT[(c4+3)*QK_PAD + row] = kv4.w;
    }
    __syncthreads();

    {
        const int tx = tid & 15, ty = tid >> 4;
        const int j0 = tx * 4, i0 = ty * 4;
        float acc[4][4] = {};
#pragma unroll 8
        for (int kk = 0; kk < 128; kk++) {
            float4 a = *(const float4*)&qT[kk * QK_PAD + i0];
            float4 bb4 = *(const float4*)&kT[kk * QK_PAD + j0];
            const float am[4] = {a.x, a.y, a.z, a.w};
            const float bm[4] = {bb4.x, bb4.y, bb4.z, bb4.w};
#pragma unroll
            for (int m = 0; m < 4; m++)
#pragma unroll
                for (int n = 0; n < 4; n++)
                    acc[m][n] += am[m] * bm[n];
        }
#pragma unroll
        for (int m = 0; m < 4; m++) {
            int i = i0 + m;
            float4 w;
            w.x = (j0 + 0 <= i) ? acc[m][0] : 0.0f;
            w.y = (j0 + 1 <= i) ? acc[m][1] : 0.0f;
            w.z = (j0 + 2 <= i) ? acc[m][2] : 0.0f;
            w.w = (j0 + 3 <= i) ? acc[m][3] : 0.0f;
            *(float4*)&S[i * 64 + j0] = w;
        }
    }
    __syncthreads();

    for (int f = tid; f < 64 * 32; f += 256) {
        int row = f >> 5;
        int c4  = (f & 31) << 2;
        float bta = beta[(tok0 + row) * NHEADS + h];
        float sp  = (bta > 20.0f) ? bta : log1pf(expf(bta));
        float4 vv = *(const float4*)(v + base + (size_t)row * tokstride + c4);
        vv.x *= sp; vv.y *= sp; vv.z *= sp; vv.w *= sp;
        *(float4*)&gvS[row * 128 + c4] = vv;
    }
    __syncthreads();

    {
        const int tx = tid & 15, ty = tid >> 4;
        const int kk0 = tx * 8, i0 = ty * 4;
        float o[4][8] = {};
        const int jend = i0 + 4;
        for (int j = 0; j < jend; j++) {
            float s0 = S[(i0+0)*64 + j];
            float s1 = S[(i0+1)*64 + j];
            float s2 = S[(i0+2)*64 + j];
            float s3 = S[(i0+3)*64 + j];
            float4 g0 = *(const float4*)&gvS[j * 128 + kk0];
            float4 g1 = *(const float4*)&gvS[j * 128 + kk0 + 4];
            const float gg[8] = {g0.x,g0.y,g0.z,g0.w,g1.x,g1.y,g1.z,g1.w};
#pragma unroll
            for (int n = 0; n < 8; n++) {
                o[0][n] += s0 * gg[n];
                o[1][n] += s1 * gg[n];
                o[2][n] += s2 * gg[n];
                o[3][n] += s3 * gg[n];
            }
        }
#pragma unroll
        for (int m = 0; m < 4; m++) {
            float* op = out + base + (size_t)(i0 + m) * tokstride + kk0;
            *(float4*)(op)     = make_float4(o[m][0], o[m][1], o[m][2], o[m][3]);
            *(float4*)(op + 4) = make_float4(o[m][4], o[m][5], o[m][6], o[m][7]);
        }
    }
}

// ---------------------------------------------------------------------------
extern "C" void kernel_launch(void* const* d_in, const int* in_sizes, int n_in,
                              void* d_out, int out_size)
{
    const float* hs   = (const float*)d_in[0];
    const float* q_w  = (const float*)d_in[1];
    const float* q_b  = (const float*)d_in[2];
    const float* k_w  = (const float*)d_in[3];
    const float* k_b  = (const float*)d_in[4];
    const float* v_w  = (const float*)d_in[5];
    const float* v_b  = (const float*)d_in[6];
    /* a_w, a_b (d_in[7], d_in[8]) are dead code in the reference */
    const float* b_w  = (const float*)d_in[9];
    const float* b_b  = (const float*)d_in[10];
    const float* og_w = (const float*)d_in[11];
    const float* o_w  = (const float*)d_in[12];
    const float* o_b  = (const float*)d_in[13];
    float* out = (float*)d_out;

    float *gq, *gk, *gv, *gog, *gao, *gbeta;
    __half *ga1, *gwq, *gwk, *gwv, *gwog, *gwo;
    cudaGetSymbolAddress((void**)&gq,    g_q);
    cudaGetSymbolAddress((void**)&gk,    g_k);
    cudaGetSymbolAddress((void**)&gv,    g_v);
    cudaGetSymbolAddress((void**)&gog,   g_og);
    cudaGetSymbolAddress((void**)&gao,   g_ao);
    cudaGetSymbolAddress((void**)&gbeta, g_beta);
    cudaGetSymbolAddress((void**)&ga1,   g_a1);
    cudaGetSymbolAddress((void**)&gwq,   g_wq);
    cudaGetSymbolAddress((void**)&gwk,   g_wk);
    cudaGetSymbolAddress((void**)&gwv,   g_wv);
    cudaGetSymbolAddress((void**)&gwog,  g_wog);
    cudaGetSymbolAddress((void**)&gwo,   g_wo);

    cudaFuncSetAttribute(gemm_f16,
                         cudaFuncAttributeMaxDynamicSharedMemorySize, GSMEM);

    const dim3 gG(QKV / 128, MROWS / 256);        // (16, 64)
    const unsigned actBlocks = (unsigned)((size_t)MROWS * HID / 4 / 256);  // 32768
    const unsigned wBlocks   = (unsigned)((size_t)QKV  * HID / 4 / 256);   // 4096

    // launches 0-4: activation convert + 4 weight converts
    cvt_half<<<actBlocks, 256>>>(hs, ga1);
    cvt_half<<<wBlocks, 256>>>(q_w,  gwq);
    cvt_half<<<wBlocks, 256>>>(k_w,  gwk);
    cvt_half<<<wBlocks, 256>>>(v_w,  gwv);
    cvt_half<<<wBlocks, 256>>>(og_w, gwog);

    // launch 5 (ncu -s 5 -c 1 profiles this one): first projection GEMM
    gemm_f16<<<gG, 512, GSMEM>>>(ga1, gwq,  q_b,    gq);
    gemm_f16<<<gG, 512, GSMEM>>>(ga1, gwk,  k_b,    gk);
    gemm_f16<<<gG, 512, GSMEM>>>(ga1, gwv,  v_b,    gv);
    gemm_f16<<<gG, 512, GSMEM>>>(ga1, gwog, nullptr, gog);

    beta_gemm<<<MROWS / 8, 256>>>(hs, b_w, b_b, gbeta);

    size_t smemA = (size_t)(2 * 128 * QK_PAD + 64 * 64) * sizeof(float);
    cudaFuncSetAttribute(attn_kernel,
                         cudaFuncAttributeMaxDynamicSharedMemorySize, (int)smemA);
    dim3 gAttn(NHEADS, SEQ / CHUNK, BATCH);
    attn_kernel<<<gAttn, 256, smemA>>>(gq, gk, gv, gbeta, gao);

    // gate into fp16 activations (reuses ga1), then output projection
    gate_half<<<actBlocks, 256>>>(gao, gog, ga1);
    cvt_half<<<wBlocks, 256>>>(o_w, gwo);
    gemm_f16<<<gG, 512, GSMEM>>>(ga1, gwo, o_b, out);
}

// round 11
// speedup vs baseline: 11.6842x; 1.0164x over previous
#include <cuda_runtime.h>
#include <cuda_fp16.h>
#include <math.h>
#include <stdint.h>

#define NHEADS 16
#define HDIM   128
#define CHUNK  64
#define BATCH  4
#define SEQ    4096
#define HID    2048
#define MROWS  (BATCH*SEQ)            /* 16384 */
#define QKV    (NHEADS*HDIM)          /* 2048  */

// ---------------- scratch (device globals; no allocation allowed) -----------
static __device__ __half g_q  [(size_t)MROWS*QKV];
static __device__ __half g_k  [(size_t)MROWS*QKV];
static __device__ __half g_v  [(size_t)MROWS*QKV];
static __device__ __half g_og [(size_t)MROWS*QKV];
static __device__ float  g_beta[(size_t)MROWS*NHEADS];
static __device__ __half g_a1 [(size_t)MROWS*HID];     // fp16 activations
static __device__ __half g_wq [(size_t)QKV*HID];
static __device__ __half g_wk [(size_t)QKV*HID];
static __device__ __half g_wv [(size_t)QKV*HID];
static __device__ __half g_wog[(size_t)QKV*HID];
static __device__ __half g_wo [(size_t)QKV*HID];

// ---------------- PTX helpers (family-PTX-safe: sm_80-era only) -------------
__device__ __forceinline__ uint32_t smem_u32(const void* p) {
    uint32_t a;
    asm("{ .reg .u64 t; cvta.to.shared.u64 t, %1; cvt.u32.u64 %0, t; }"
        : "=r"(a) : "l"(p));
    return a;
}
__device__ __forceinline__ void cpa16(uint32_t d, const void* s) {
    asm volatile("cp.async.cg.shared.global [%0], [%1], 16;" :: "r"(d), "l"(s));
}
__device__ __forceinline__ void cp_commit() {
    asm volatile("cp.async.commit_group;" ::: "memory");
}
__device__ __forceinline__ void cp_wait3() {
    asm volatile("cp.async.wait_group 3;" ::: "memory");
}
__device__ __forceinline__ void ldsm4(uint32_t& r0, uint32_t& r1,
                                      uint32_t& r2, uint32_t& r3, uint32_t a) {
    asm volatile("ldmatrix.sync.aligned.m8n8.x4.shared.b16 {%0,%1,%2,%3}, [%4];"
                 : "=r"(r0), "=r"(r1), "=r"(r2), "=r"(r3) : "r"(a));
}
__device__ __forceinline__ void mma16816(float* c, const uint32_t* a,
                                         uint32_t b0, uint32_t b1) {
    asm volatile(
        "mma.sync.aligned.m16n8k16.row.col.f32.f16.f16.f32 "
        "{%0,%1,%2,%3}, {%4,%5,%6,%7}, {%8,%9}, {%0,%1,%2,%3};"
        : "+f"(c[0]), "+f"(c[1]), "+f"(c[2]), "+f"(c[3])
        : "r"(a[0]), "r"(a[1]), "r"(a[2]), "r"(a[3]), "r"(b0), "r"(b1));
}

// typed pair-store: fp32 or fp16 output
__device__ __forceinline__ void st2(float* p, float x, float y) {
    *(float2*)p = make_float2(x, y);
}
__device__ __forceinline__ void st2(__half* p, float x, float y) {
    *(__half2*)p = __floats2half2_rn(x, y);
}

// ---------------------------------------------------------------------------
// mma.sync fp16 GEMM: C[M,2048] = A[M,2048] @ W[2048,2048]^T (+bias)
// CTA tile 256x128, 512 threads (16 warps, warp tile 64x32).
// 32 chunks of 64 k-cols; stage = A 32KB + W 16KB = 48KB; 4-stage cp.async.
// ---------------------------------------------------------------------------
#define NSC       32
#define OFF_A     0
#define OFF_W     32768
#define STG_BYTES 49152
#define GSMEM     (4*STG_BYTES)          /* 196608 */

template <typename OutT>
__global__ __launch_bounds__(512, 1)
void gemm_f16(const __half* __restrict__ A, const __half* __restrict__ W,
              const float* __restrict__ bias, OutT* __restrict__ C)
{
    extern __shared__ __align__(1024) char smem[];
    const uint32_t sb = smem_u32(smem);
    const int tid = threadIdx.x;
    const int bn0 = blockIdx.x * 128;
    const int bm0 = blockIdx.y * 256;

    // ---- loader geometry ----
    const int r0  = tid >> 3;             // 0..63
    const int c16 = (tid & 7) * 16;       // byte offset within 128B chunk-row
    const size_t rowHB = (size_t)HID * 2; // 4096 B row stride (A and W)

    const char* abase = (const char*)A + (size_t)bm0 * rowHB + c16;
    const char* wbase = (const char*)W + (size_t)bn0 * rowHB + c16;

    auto load_stage = [&](int sc, int s) {
        const uint32_t st = sb + s * STG_BYTES;
        const char* ap = abase + (size_t)sc * 128;
        const char* wp = wbase + (size_t)sc * 128;
#pragma unroll
        for (int i = 0; i < 4; i++) {
            const int row = r0 + i * 64;
            uint32_t off = (uint32_t)row * 128 + (uint32_t)c16;
            uint32_t sw  = off ^ ((off >> 3) & 0x70);
            cpa16(st + OFF_A + sw, ap + (size_t)row * rowHB);
        }
#pragma unroll
        for (int i = 0; i < 2; i++) {
            const int row = r0 + i * 64;
            uint32_t off = (uint32_t)row * 128 + (uint32_t)c16;
            uint32_t sw  = off ^ ((off >> 3) & 0x70);
            cpa16(st + OFF_W + sw, wp + (size_t)row * rowHB);
        }
        cp_commit();
    };

    // ---- warp fragment geometry ----
    const int lane = tid & 31;
    const int warp = tid >> 5;
    const int wm = warp >> 2;            // 0..3  -> 64-row block
    const int wn = warp & 3;             // 0..3  -> 32-col block

    const int a_row  = wm * 64 + (lane & 15);
    const int a_sel  = (lane >> 4) * 16;
    const uint32_t a_x = (uint32_t)((a_row & 7) << 4);
    const int b_row  = wn * 32 + ((lane >> 4) << 3) + (lane & 7);
    const int b_sel  = ((lane >> 3) & 1) * 16;
    const uint32_t b_x = (uint32_t)((b_row & 7) << 4);

    float acc[4][4][4];
#pragma unroll
    for (int i = 0; i < 4; i++)
#pragma unroll
        for (int j = 0; j < 4; j++)
#pragma unroll
            for (int r = 0; r < 4; r++) acc[i][j][r] = 0.0f;

    // prologue: fill 4 stages
    load_stage(0, 0);
    load_stage(1, 1);
    load_stage(2, 2);
    load_stage(3, 3);

    for (int sc = 0; sc < NSC; sc++) {
        const int s = sc & 3;
        cp_wait3();
        __syncthreads();

        const uint32_t st = sb + s * STG_BYTES;

#pragma unroll
        for (int ks = 0; ks < 4; ks++) {
            const uint32_t kb = (uint32_t)(ks * 32);
            uint32_t b[2][4];
#pragma unroll
            for (int nb = 0; nb < 2; nb++) {
                uint32_t broff = (uint32_t)(b_row + nb * 16) * 128
                               + ((kb + (uint32_t)b_sel) ^ b_x);
                ldsm4(b[nb][0], b[nb][1], b[nb][2], b[nb][3], st + OFF_W + broff);
            }
#pragma unroll
            for (int mf = 0; mf < 4; mf++) {
                uint32_t aroff = (uint32_t)(a_row + mf * 16) * 128
                               + ((kb + (uint32_t)a_sel) ^ a_x);
                uint32_t a[4];
                ldsm4(a[0], a[1], a[2], a[3], st + OFF_A + aroff);
                mma16816(acc[mf][0], a, b[0][0], b[0][1]);
                mma16816(acc[mf][1], a, b[0][2], b[0][3]);
                mma16816(acc[mf][2], a, b[1][0], b[1][1]);
                mma16816(acc[mf][3], a, b[1][2], b[1][3]);
            }
        }
        __syncthreads();

        if (sc + 4 < NSC) {
            load_stage(sc + 4, s);
        } else {
            cp_commit();   // keep group count uniform for cp_wait3
        }
    }

    // ---- epilogue ----
#pragma unroll
    for (int nf = 0; nf < 4; nf++) {
        const int col = bn0 + wn * 32 + nf * 8 + (lane & 3) * 2;
        float b0 = 0.0f, b1 = 0.0f;
        if (bias) { b0 = bias[col]; b1 = bias[col + 1]; }
#pragma unroll
        for (int mf = 0; mf < 4; mf++) {
            const int row = bm0 + wm * 64 + mf * 16 + (lane >> 2);
            st2(C + (size_t)row * QKV + col,       acc[mf][nf][0] + b0,
                                                   acc[mf][nf][1] + b1);
            st2(C + (size_t)(row + 8) * QKV + col, acc[mf][nf][2] + b0,
                                                   acc[mf][nf][3] + b1);
        }
    }
}

// ---------------------------------------------------------------------------
// fp32 -> fp16 pack helper
// ---------------------------------------------------------------------------
__device__ __forceinline__ uint2 pack4h(float x, float y, float z, float w) {
    __half2 a = __floats2half2_rn(x, y);
    __half2 b = __floats2half2_rn(z, w);
    uint2 r;
    r.x = *(uint32_t*)&a;
    r.y = *(uint32_t*)&b;
    return r;
}

// all 5 weight matrices fp32 -> fp16 in one launch (blockIdx.y selects tensor)
__global__ __launch_bounds__(256)
void wconv5(const float* __restrict__ w0, const float* __restrict__ w1,
            const float* __restrict__ w2, const float* __restrict__ w3,
            const float* __restrict__ w4,
            __half* __restrict__ o0, __half* __restrict__ o1,
            __half* __restrict__ o2, __half* __restrict__ o3,
            __half* __restrict__ o4)
{
    const float* in;
    __half* out;
    switch (blockIdx.y) {
        case 0: in = w0; out = o0; break;
        case 1: in = w1; out = o1; break;
        case 2: in = w2; out = o2; break;
        case 3: in = w3; out = o3; break;
        default: in = w4; out = o4; break;
    }
    size_t i = ((size_t)blockIdx.x * 256 + threadIdx.x) * 4;
    float4 v = *(const float4*)(in + i);
    *(uint2*)(out + i) = pack4h(v.x, v.y, v.z, v.w);
}

// ---------------------------------------------------------------------------
// beta = hs @ b_w^T + b_b  (N=16), fp32; ALSO emits fp16 copy of hs (fused
// activation convert — each warp streams one full hs row anyway).
// ---------------------------------------------------------------------------
__global__ __launch_bounds__(256)
void beta_gemm(const float* __restrict__ hs, const float* __restrict__ bw,
               const float* __restrict__ bb, float* __restrict__ beta,
               __half* __restrict__ a16)
{
    int warp = (blockIdx.x * blockDim.x + threadIdx.x) >> 5;
    int lane = threadIdx.x & 31;
    if (warp >= MROWS) return;
    const float* x = hs + (size_t)warp * HID;
    __half* xo = a16 + (size_t)warp * HID;

    float acc[NHEADS];
#pragma unroll
    for (int j = 0; j < NHEADS; j++) acc[j] = 0.0f;

    for (int t = 0; t < HID / 128; t++) {
        int k = t * 128 + lane * 4;
        float4 xv = *(const float4*)(x + k);
        *(uint2*)(xo + k) = pack4h(xv.x, xv.y, xv.z, xv.w);
#pragma unroll
        for (int j = 0; j < NHEADS; j++) {
            float4 wv = *(const float4*)(bw + (size_t)j * HID + k);
            acc[j] += xv.x*wv.x + xv.y*wv.y + xv.z*wv.z + xv.w*wv.w;
        }
    }
#pragma unroll
    for (int j = 0; j < NHEADS; j++)
#pragma unroll
        for (int off = 16; off > 0; off >>= 1)
            acc[j] += __shfl_xor_sync(0xffffffffu, acc[j], off);

    if (lane < NHEADS) {
        float v = 0.0f;
#pragma unroll
        for (int j = 0; j < NHEADS; j++) if (lane == j) v = acc[j];
        beta[(size_t)warp * NHEADS + lane] = v + bb[lane];
    }
}

// ---------------------------------------------------------------------------
// Chunk attention, fully fused:
//   inputs q,k,v,og in fp16; l2norm(q), l2norm(k) during load (warp shfl);
//   gv = softplus(beta)*v; S = tril(Qc Kc^T); O = S @ GVc;
//   output = O * silu(og) written as fp16 activations for the final GEMM.
// ---------------------------------------------------------------------------
#define QK_PAD 68
__global__ __launch_bounds__(256)
void attn_kernel(const __half* __restrict__ q, const __half* __restrict__ k,
                 const __half* __restrict__ v, const __half* __restrict__ og,
                 const float* __restrict__ beta, __half* __restrict__ outa)
{
    extern __shared__ float sm[];
    float* qT  = sm;
    float* kT  = qT + 128 * QK_PAD;
    float* S   = kT + 128 * QK_PAD;
    float* gvS = qT;

    const int h  = blockIdx.x;
    const int cn = blockIdx.y;
    const int b  = blockIdx.z;
    const int tid = threadIdx.x;

    const size_t tok0 = (size_t)b * SEQ + (size_t)cn * CHUNK;
    const size_t base = (tok0 * NHEADS + h) * HDIM;   // token stride = 2048
    const int tokstride = NHEADS * HDIM;
    const float eps_n = 1.1313708499e-11f;   // sqrt(128) * 1e-12

    // phase 1: load q,k (fp16 -> fp32), l2-normalize per row, store transposed
    for (int f = tid; f < 64 * 32; f += 256) {
        int row = f >> 5;
        int c4  = (f & 31) << 2;
        size_t g = base + (size_t)row * tokstride + c4;
        uint2 qr = *(const uint2*)(q + g);
        uint2 kr = *(const uint2*)(k + g);
        float2 q01 = __half22float2(*(__half2*)&qr.x);
        float2 q23 = __half22float2(*(__half2*)&qr.y);
        float2 k01 = __half22float2(*(__half2*)&kr.x);
        float2 k23 = __half22float2(*(__half2*)&kr.y);

        float sq = q01.x*q01.x + q01.y*q01.y + q23.x*q23.x + q23.y*q23.y;
        float sk = k01.x*k01.x + k01.y*k01.y + k23.x*k23.x + k23.y*k23.y;
#pragma unroll
        for (int off = 16; off > 0; off >>= 1) {
            sq += __shfl_xor_sync(0xffffffffu, sq, off);
            sk += __shfl_xor_sync(0xffffffffu, sk, off);
        }
        float fq = 1.0f / fmaxf(sqrtf(sq), eps_n);
        float fk = 1.0f / fmaxf(sqrtf(sk), eps_n);

        qT[(c4+0)*QK_PAD + row] = q01.x * fq;
        qT[(c4+1)*QK_PAD + row] = q01.y * fq;
        qT[(c4+2)*QK_PAD + row] = q23.x * fq;
        qT[(c4+3)*QK_PAD + row] = q23.y * fq;
        kT[(c4+0)*QK_PAD + row] = k01.x * fk;
        kT[(c4+1)*QK_PAD + row] = k01.y * fk;
        kT[(c4+2)*QK_PAD + row] = k23.x * fk;
        kT[(c4+3)*QK_PAD + row] = k23.y * fk;
    }
    __syncthreads();

    // phase 2: S[i][j] = qn_i . kn_j, masked to tril
    {
        const int tx = tid & 15, ty = tid >> 4;
        const int j0 = tx * 4, i0 = ty * 4;
        float acc[4][4] = {};
#pragma unroll 8
        for (int kk = 0; kk < 128; kk++) {
            float4 a = *(const float4*)&qT[kk * QK_PAD + i0];
            float4 bb4 = *(const float4*)&kT[kk * QK_PAD + j0];
            const float am[4] = {a.x, a.y, a.z, a.w};
            const float bm[4] = {bb4.x, bb4.y, bb4.z, bb4.w};
#pragma unroll
            for (int m = 0; m < 4; m++)
#pragma unroll
                for (int n = 0; n < 4; n++)
                    acc[m][n] += am[m] * bm[n];
        }
#pragma unroll
        for (int m = 0; m < 4; m++) {
            int i = i0 + m;
            float4 w;
            w.x = (j0 + 0 <= i) ? acc[m][0] : 0.0f;
            w.y = (j0 + 1 <= i) ? acc[m][1] : 0.0f;
            w.z = (j0 + 2 <= i) ? acc[m][2] : 0.0f;
            w.w = (j0 + 3 <= i) ? acc[m][3] : 0.0f;
            *(float4*)&S[i * 64 + j0] = w;
        }
    }
    __syncthreads();

    // load gv = softplus(beta) * v (fp16 -> fp32) into qT region
    for (int f = tid; f < 64 * 32; f += 256) {
        int row = f >> 5;
        int c4  = (f & 31) << 2;
        float bta = beta[(tok0 + row) * NHEADS + h];
        float sp  = (bta > 20.0f) ? bta : log1pf(expf(bta));
        uint2 vr = *(const uint2*)(v + base + (size_t)row * tokstride + c4);
        float2 v01 = __half22float2(*(__half2*)&vr.x);
        float2 v23 = __half22float2(*(__half2*)&vr.y);
        float4 vv = make_float4(v01.x * sp, v01.y * sp, v23.x * sp, v23.y * sp);
        *(float4*)&gvS[row * 128 + c4] = vv;
    }
    __syncthreads();

    // phase 3: O[i][:] = sum_{j<=i} S[i][j]*gv[j][:]; gate with silu(og); fp16 out
    {
        const int tx = tid & 15, ty = tid >> 4;
        const int kk0 = tx * 8, i0 = ty * 4;
        float o[4][8] = {};
        const int jend = i0 + 4;
        for (int j = 0; j < jend; j++) {
            float s0 = S[(i0+0)*64 + j];
            float s1 = S[(i0+1)*64 + j];
            float s2 = S[(i0+2)*64 + j];
            float s3 = S[(i0+3)*64 + j];
            float4 g0 = *(const float4*)&gvS[j * 128 + kk0];
            float4 g1 = *(const float4*)&gvS[j * 128 + kk0 + 4];
            const float gg[8] = {g0.x,g0.y,g0.z,g0.w,g1.x,g1.y,g1.z,g1.w};
#pragma unroll
            for (int n = 0; n < 8; n++) {
                o[0][n] += s0 * gg[n];
                o[1][n] += s1 * gg[n];
                o[2][n] += s2 * gg[n];
                o[3][n] += s3 * gg[n];
            }
        }
#pragma unroll
        for (int m = 0; m < 4; m++) {
            const size_t roff = base + (size_t)(i0 + m) * tokstride + kk0;
            uint2 ogr0 = *(const uint2*)(og + roff);
            uint2 ogr1 = *(const uint2*)(og + roff + 4);
            float2 ga = __half22float2(*(__half2*)&ogr0.x);
            float2 gb = __half22float2(*(__half2*)&ogr0.y);
            float2 gc = __half22float2(*(__half2*)&ogr1.x);
            float2 gd = __half22float2(*(__half2*)&ogr1.y);
            const float gx[8] = {ga.x, ga.y, gb.x, gb.y, gc.x, gc.y, gd.x, gd.y};
            float y[8];
#pragma unroll
            for (int n = 0; n < 8; n++)
                y[n] = o[m][n] * (gx[n] / (1.0f + expf(-gx[n])));
            uint2 p0 = pack4h(y[0], y[1], y[2], y[3]);
            uint2 p1 = pack4h(y[4], y[5], y[6], y[7]);
            *(uint2*)(outa + roff)     = p0;
            *(uint2*)(outa + roff + 4) = p1;
        }
    }
}

// ---------------------------------------------------------------------------
extern "C" void kernel_launch(void* const* d_in, const int* in_sizes, int n_in,
                              void* d_out, int out_size)
{
    const float* hs   = (const float*)d_in[0];
    const float* q_w  = (const float*)d_in[1];
    const float* q_b  = (const float*)d_in[2];
    const float* k_w  = (const float*)d_in[3];
    const float* k_b  = (const float*)d_in[4];
    const float* v_w  = (const float*)d_in[5];
    const float* v_b  = (const float*)d_in[6];
    /* a_w, a_b (d_in[7], d_in[8]) are dead code in the reference */
    const float* b_w  = (const float*)d_in[9];
    const float* b_b  = (const float*)d_in[10];
    const float* og_w = (const float*)d_in[11];
    const float* o_w  = (const float*)d_in[12];
    const float* o_b  = (const float*)d_in[13];
    float* out = (float*)d_out;

    float *gbeta;
    __half *gq, *gk, *gv, *gog, *ga1, *gwq, *gwk, *gwv, *gwog, *gwo;
    cudaGetSymbolAddress((void**)&gq,    g_q);
    cudaGetSymbolAddress((void**)&gk,    g_k);
    cudaGetSymbolAddress((void**)&gv,    g_v);
    cudaGetSymbolAddress((void**)&gog,   g_og);
    cudaGetSymbolAddress((void**)&gbeta, g_beta);
    cudaGetSymbolAddress((void**)&ga1,   g_a1);
    cudaGetSymbolAddress((void**)&gwq,   g_wq);
    cudaGetSymbolAddress((void**)&gwk,   g_wk);
    cudaGetSymbolAddress((void**)&gwv,   g_wv);
    cudaGetSymbolAddress((void**)&gwog,  g_wog);
    cudaGetSymbolAddress((void**)&gwo,   g_wo);

    cudaFuncSetAttribute(gemm_f16<__half>,
                         cudaFuncAttributeMaxDynamicSharedMemorySize, GSMEM);
    cudaFuncSetAttribute(gemm_f16<float>,
                         cudaFuncAttributeMaxDynamicSharedMemorySize, GSMEM);

    const dim3 gG(QKV / 128, MROWS / 256);        // (16, 64)
    const unsigned wBlocks = (unsigned)((size_t)QKV * HID / 4 / 256);   // 4096

    // launch 0: beta GEMM + fused fp16 activation convert
    beta_gemm<<<MROWS / 8, 256>>>(hs, b_w, b_b, gbeta, ga1);

    // launch 1: all 5 weight converts
    wconv5<<<dim3(wBlocks, 5), 256>>>(q_w, k_w, v_w, og_w, o_w,
                                      gwq, gwk, gwv, gwog, gwo);

    // launches 2-5: projection GEMMs (fp16 outputs)
    gemm_f16<__half><<<gG, 512, GSMEM>>>(ga1, gwq,  q_b,    gq);
    gemm_f16<__half><<<gG, 512, GSMEM>>>(ga1, gwk,  k_b,    gk);
    gemm_f16<__half><<<gG, 512, GSMEM>>>(ga1, gwv,  v_b,    gv);
    gemm_f16<__half><<<gG, 512, GSMEM>>>(ga1, gwog, nullptr, gog);

    // launch 6: fused attention (+l2norm, +softplus, +silu gate, fp16 out -> ga1)
    size_t smemA = (size_t)(2 * 128 * QK_PAD + 64 * 64) * sizeof(float);
    cudaFuncSetAttribute(attn_kernel,
                         cudaFuncAttributeMaxDynamicSharedMemorySize, (int)smemA);
    dim3 gAttn(NHEADS, SEQ / CHUNK, BATCH);
    attn_kernel<<<gAttn, 256, smemA>>>(gq, gk, gv, gog, gbeta, ga1);

    // launch 7: output projection (fp32 out)
    gemm_f16<float><<<gG, 512, GSMEM>>>(ga1, gwo, o_b, out);
}

// round 12
// speedup vs baseline: 12.6965x; 1.0866x over previous
#include <cuda_runtime.h>
#include <cuda_fp16.h>
#include <math.h>
#include <stdint.h>

#define NHEADS 16
#define HDIM   128
#define CHUNK  64
#define BATCH  4
#define SEQ    4096
#define HID    2048
#define MROWS  (BATCH*SEQ)            /* 16384 */
#define QKV    (NHEADS*HDIM)          /* 2048  */

// ---------------- scratch (device globals; no allocation allowed) -----------
static __device__ __half g_q  [(size_t)MROWS*QKV];
static __device__ __half g_k  [(size_t)MROWS*QKV];
static __device__ __half g_v  [(size_t)MROWS*QKV];
static __device__ __half g_og [(size_t)MROWS*QKV];
static __device__ float  g_beta[(size_t)MROWS*NHEADS];
static __device__ __half g_a1 [(size_t)MROWS*HID];     // fp16 activations
static __device__ __half g_wq [(size_t)QKV*HID];
static __device__ __half g_wk [(size_t)QKV*HID];
static __device__ __half g_wv [(size_t)QKV*HID];
static __device__ __half g_wog[(size_t)QKV*HID];
static __device__ __half g_wo [(size_t)QKV*HID];

// ---------------- PTX helpers (family-PTX-safe: sm_80-era only) -------------
__device__ __forceinline__ uint32_t smem_u32(const void* p) {
    uint32_t a;
    asm("{ .reg .u64 t; cvta.to.shared.u64 t, %1; cvt.u32.u64 %0, t; }"
        : "=r"(a) : "l"(p));
    return a;
}
__device__ __forceinline__ void cpa16(uint32_t d, const void* s) {
    asm volatile("cp.async.cg.shared.global [%0], [%1], 16;" :: "r"(d), "l"(s));
}
__device__ __forceinline__ void cp_commit() {
    asm volatile("cp.async.commit_group;" ::: "memory");
}
__device__ __forceinline__ void cp_wait1() {
    asm volatile("cp.async.wait_group 1;" ::: "memory");
}
__device__ __forceinline__ void ldsm4(uint32_t& r0, uint32_t& r1,
                                      uint32_t& r2, uint32_t& r3, uint32_t a) {
    asm volatile("ldmatrix.sync.aligned.m8n8.x4.shared.b16 {%0,%1,%2,%3}, [%4];"
                 : "=r"(r0), "=r"(r1), "=r"(r2), "=r"(r3) : "r"(a));
}
__device__ __forceinline__ void mma16816(float* c, const uint32_t* a,
                                         uint32_t b0, uint32_t b1) {
    asm volatile(
        "mma.sync.aligned.m16n8k16.row.col.f32.f16.f16.f32 "
        "{%0,%1,%2,%3}, {%4,%5,%6,%7}, {%8,%9}, {%0,%1,%2,%3};"
        : "+f"(c[0]), "+f"(c[1]), "+f"(c[2]), "+f"(c[3])
        : "r"(a[0]), "r"(a[1]), "r"(a[2]), "r"(a[3]), "r"(b0), "r"(b1));
}

// typed pair-store: fp32 or fp16 output
__device__ __forceinline__ void st2(float* p, float x, float y) {
    *(float2*)p = make_float2(x, y);
}
__device__ __forceinline__ void st2(__half* p, float x, float y) {
    *(__half2*)p = __floats2half2_rn(x, y);
}

// ---------------------------------------------------------------------------
// mma.sync fp16 GEMM: C[M,2048] = A[M,2048] @ W[2048,2048]^T (+bias)
// CTA tile 128x128, 256 threads (8 warps, warp tile 64x32).
// 32 chunks of 64 k-cols; stage = A 16KB + W 16KB = 32KB; 3-stage cp.async
// pipeline (96KB smem) -> 2 CTAs/SM for cross-CTA latency hiding.
// One __syncthreads per chunk (3-stage rotation makes the 2nd redundant).
// ---------------------------------------------------------------------------
#define NSC       32
#define OFF_A     0
#define OFF_W     16384
#define STG_BYTES 32768
#define GSMEM     (3*STG_BYTES)          /* 98304 */

template <typename OutT>
__global__ __launch_bounds__(256, 2)
void gemm_f16(const __half* __restrict__ A, const __half* __restrict__ W,
              const float* __restrict__ bias, OutT* __restrict__ C)
{
    extern __shared__ __align__(1024) char smem[];
    const uint32_t sb = smem_u32(smem);
    const int tid = threadIdx.x;
    const int bn0 = blockIdx.x * 128;
    const int bm0 = blockIdx.y * 128;

    // ---- loader geometry: 32 rows x 8 x 16B segments per pass ----
    const int r0  = tid >> 3;             // 0..31
    const int c16 = (tid & 7) * 16;       // byte offset within 128B chunk-row
    const size_t rowHB = (size_t)HID * 2; // 4096 B row stride (A and W)

    const char* abase = (const char*)A + (size_t)bm0 * rowHB + c16;
    const char* wbase = (const char*)W + (size_t)bn0 * rowHB + c16;

    auto load_stage = [&](int sc, int s) {
        const uint32_t st = sb + s * STG_BYTES;
        const char* ap = abase + (size_t)sc * 128;
        const char* wp = wbase + (size_t)sc * 128;
#pragma unroll
        for (int i = 0; i < 4; i++) {
            const int row = r0 + i * 32;
            uint32_t off = (uint32_t)row * 128 + (uint32_t)c16;
            uint32_t sw  = off ^ ((off >> 3) & 0x70);
            cpa16(st + OFF_A + sw, ap + (size_t)row * rowHB);
            cpa16(st + OFF_W + sw, wp + (size_t)row * rowHB);
        }
        cp_commit();
    };

    // ---- warp fragment geometry ----
    const int lane = tid & 31;
    const int warp = tid >> 5;
    const int wm = warp >> 2;            // 0..1  -> 64-row block
    const int wn = warp & 3;             // 0..3  -> 32-col block

    const int a_row  = wm * 64 + (lane & 15);
    const int a_sel  = (lane >> 4) * 16;
    const uint32_t a_x = (uint32_t)((a_row & 7) << 4);
    const int b_row  = wn * 32 + ((lane >> 4) << 3) + (lane & 7);
    const int b_sel  = ((lane >> 3) & 1) * 16;
    const uint32_t b_x = (uint32_t)((b_row & 7) << 4);

    float acc[4][4][4];
#pragma unroll
    for (int i = 0; i < 4; i++)
#pragma unroll
        for (int j = 0; j < 4; j++)
#pragma unroll
            for (int r = 0; r < 4; r++) acc[i][j][r] = 0.0f;

    // prologue: 2 stages in flight
    load_stage(0, 0);
    load_stage(1, 1);

    for (int sc = 0; sc < NSC; sc++) {
        const int s = sc % 3;
        cp_wait1();            // oldest pending group (chunk sc) complete
        __syncthreads();       // all warps done with chunk sc-1's stage

        // refill the stage chunk sc-1 occupied (provably consumed)
        if (sc + 2 < NSC) load_stage(sc + 2, (sc + 2) % 3);
        else              cp_commit();   // keep group count uniform

        const uint32_t st = sb + s * STG_BYTES;

#pragma unroll
        for (int ks = 0; ks < 4; ks++) {
            const uint32_t kb = (uint32_t)(ks * 32);
            uint32_t b[2][4];
#pragma unroll
            for (int nb = 0; nb < 2; nb++) {
                uint32_t broff = (uint32_t)(b_row + nb * 16) * 128
                               + ((kb + (uint32_t)b_sel) ^ b_x);
                ldsm4(b[nb][0], b[nb][1], b[nb][2], b[nb][3], st + OFF_W + broff);
            }
#pragma unroll
            for (int mf = 0; mf < 4; mf++) {
                uint32_t aroff = (uint32_t)(a_row + mf * 16) * 128
                               + ((kb + (uint32_t)a_sel) ^ a_x);
                uint32_t a[4];
                ldsm4(a[0], a[1], a[2], a[3], st + OFF_A + aroff);
                mma16816(acc[mf][0], a, b[0][0], b[0][1]);
                mma16816(acc[mf][1], a, b[0][2], b[0][3]);
                mma16816(acc[mf][2], a, b[1][0], b[1][1]);
                mma16816(acc[mf][3], a, b[1][2], b[1][3]);
            }
        }
    }

    // ---- epilogue ----
#pragma unroll
    for (int nf = 0; nf < 4; nf++) {
        const int col = bn0 + wn * 32 + nf * 8 + (lane & 3) * 2;
        float b0 = 0.0f, b1 = 0.0f;
        if (bias) { b0 = bias[col]; b1 = bias[col + 1]; }
#pragma unroll
        for (int mf = 0; mf < 4; mf++) {
            const int row = bm0 + wm * 64 + mf * 16 + (lane >> 2);
            st2(C + (size_t)row * QKV + col,       acc[mf][nf][0] + b0,
                                                   acc[mf][nf][1] + b1);
            st2(C + (size_t)(row + 8) * QKV + col, acc[mf][nf][2] + b0,
                                                   acc[mf][nf][3] + b1);
        }
    }
}

// ---------------------------------------------------------------------------
// fp32 -> fp16 pack helper
// ---------------------------------------------------------------------------
__device__ __forceinline__ uint2 pack4h(float x, float y, float z, float w) {
    __half2 a = __floats2half2_rn(x, y);
    __half2 b = __floats2half2_rn(z, w);
    uint2 r;
    r.x = *(uint32_t*)&a;
    r.y = *(uint32_t*)&b;
    return r;
}

// all 5 weight matrices fp32 -> fp16 in one launch (blockIdx.y selects tensor)
__global__ __launch_bounds__(256)
void wconv5(const float* __restrict__ w0, const float* __restrict__ w1,
            const float* __restrict__ w2, const float* __restrict__ w3,
            const float* __restrict__ w4,
            __half* __restrict__ o0, __half* __restrict__ o1,
            __half* __restrict__ o2, __half* __restrict__ o3,
            __half* __restrict__ o4)
{
    const float* in;
    __half* out;
    switch (blockIdx.y) {
        case 0: in = w0; out = o0; break;
        case 1: in = w1; out = o1; break;
        case 2: in = w2; out = o2; break;
        case 3: in = w3; out = o3; break;
        default: in = w4; out = o4; break;
    }
    size_t i = ((size_t)blockIdx.x * 256 + threadIdx.x) * 4;
    float4 v = *(const float4*)(in + i);
    *(uint2*)(out + i) = pack4h(v.x, v.y, v.z, v.w);
}

// ---------------------------------------------------------------------------
// beta = hs @ b_w^T + b_b  (N=16), fp32; ALSO emits fp16 copy of hs (fused
// activation convert — each warp streams one full hs row anyway).
// ---------------------------------------------------------------------------
__global__ __launch_bounds__(256)
void beta_gemm(const float* __restrict__ hs, const float* __restrict__ bw,
               const float* __restrict__ bb, float* __restrict__ beta,
               __half* __restrict__ a16)
{
    int warp = (blockIdx.x * blockDim.x + threadIdx.x) >> 5;
    int lane = threadIdx.x & 31;
    if (warp >= MROWS) return;
    const float* x = hs + (size_t)warp * HID;
    __half* xo = a16 + (size_t)warp * HID;

    float acc[NHEADS];
#pragma unroll
    for (int j = 0; j < NHEADS; j++) acc[j] = 0.0f;

    for (int t = 0; t < HID / 128; t++) {
        int k = t * 128 + lane * 4;
        float4 xv = *(const float4*)(x + k);
        *(uint2*)(xo + k) = pack4h(xv.x, xv.y, xv.z, xv.w);
#pragma unroll
        for (int j = 0; j < NHEADS; j++) {
            float4 wv = *(const float4*)(bw + (size_t)j * HID + k);
            acc[j] += xv.x*wv.x + xv.y*wv.y + xv.z*wv.z + xv.w*wv.w;
        }
    }
#pragma unroll
    for (int j = 0; j < NHEADS; j++)
#pragma unroll
        for (int off = 16; off > 0; off >>= 1)
            acc[j] += __shfl_xor_sync(0xffffffffu, acc[j], off);

    if (lane < NHEADS) {
        float v = 0.0f;
#pragma unroll
        for (int j = 0; j < NHEADS; j++) if (lane == j) v = acc[j];
        beta[(size_t)warp * NHEADS + lane] = v + bb[lane];
    }
}

// ---------------------------------------------------------------------------
// Chunk attention, fully fused:
//   inputs q,k,v,og in fp16; l2norm(q), l2norm(k) during load (warp shfl);
//   gv = softplus(beta)*v; S = tril(Qc Kc^T); O = S @ GVc;
//   output = O * silu(og) written as fp16 activations for the final GEMM.
// ---------------------------------------------------------------------------
#define QK_PAD 68
__global__ __launch_bounds__(256)
void attn_kernel(const __half* __restrict__ q, const __half* __restrict__ k,
                 const __half* __restrict__ v, const __half* __restrict__ og,
                 const float* __restrict__ beta, __half* __restrict__ outa)
{
    extern __shared__ float sm[];
    float* qT  = sm;
    float* kT  = qT + 128 * QK_PAD;
    float* S   = kT + 128 * QK_PAD;
    float* gvS = qT;

    const int h  = blockIdx.x;
    const int cn = blockIdx.y;
    const int b  = blockIdx.z;
    const int tid = threadIdx.x;

    const size_t tok0 = (size_t)b * SEQ + (size_t)cn * CHUNK;
    const size_t base = (tok0 * NHEADS + h) * HDIM;   // token stride = 2048
    const int tokstride = NHEADS * HDIM;
    const float eps_n = 1.1313708499e-11f;   // sqrt(128) * 1e-12

    // phase 1: load q,k (fp16 -> fp32), l2-normalize per row, store transposed
    for (int f = tid; f < 64 * 32; f += 256) {
        int row = f >> 5;
        int c4  = (f & 31) << 2;
        size_t g = base + (size_t)row * tokstride + c4;
        uint2 qr = *(const uint2*)(q + g);
        uint2 kr = *(const uint2*)(k + g);
        float2 q01 = __half22float2(*(__half2*)&qr.x);
        float2 q23 = __half22float2(*(__half2*)&qr.y);
        float2 k01 = __half22float2(*(__half2*)&kr.x);
        float2 k23 = __half22float2(*(__half2*)&kr.y);

        float sq = q01.x*q01.x + q01.y*q01.y + q23.x*q23.x + q23.y*q23.y;
        float sk = k01.x*k01.x + k01.y*k01.y + k23.x*k23.x + k23.y*k23.y;
#pragma unroll
        for (int off = 16; off > 0; off >>= 1) {
            sq += __shfl_xor_sync(0xffffffffu, sq, off);
            sk += __shfl_xor_sync(0xffffffffu, sk, off);
        }
        float fq = 1.0f / fmaxf(sqrtf(sq), eps_n);
        float fk = 1.0f / fmaxf(sqrtf(sk), eps_n);

        qT[(c4+0)*QK_PAD + row] = q01.x * fq;
        qT[(c4+1)*QK_PAD + row] = q01.y * fq;
        qT[(c4+2)*QK_PAD + row] = q23.x * fq;
        qT[(c4+3)*QK_PAD + row] = q23.y * fq;
        kT[(c4+0)*QK_PAD + row] = k01.x * fk;
        kT[(c4+1)*QK_PAD + row] = k01.y * fk;
        kT[(c4+2)*QK_PAD + row] = k23.x * fk;
        kT[(c4+3)*QK_PAD + row] = k23.y * fk;
    }
    __syncthreads();

    // phase 2: S[i][j] = qn_i . kn_j, masked to tril
    {
        const int tx = tid & 15, ty = tid >> 4;
        const int j0 = tx * 4, i0 = ty * 4;
        float acc[4][4] = {};
#pragma unroll 8
        for (int kk = 0; kk < 128; kk++) {
            float4 a = *(const float4*)&qT[kk * QK_PAD + i0];
            float4 bb4 = *(const float4*)&kT[kk * QK_PAD + j0];
            const float am[4] = {a.x, a.y, a.z, a.w};
            const float bm[4] = {bb4.x, bb4.y, bb4.z, bb4.w};
#pragma unroll
            for (int m = 0; m < 4; m++)
#pragma unroll
                for (int n = 0; n < 4; n++)
                    acc[m][n] += am[m] * bm[n];
        }
#pragma unroll
        for (int m = 0; m < 4; m++) {
            int i = i0 + m;
            float4 w;
            w.x = (j0 + 0 <= i) ? acc[m][0] : 0.0f;
            w.y = (j0 + 1 <= i) ? acc[m][1] : 0.0f;
            w.z = (j0 + 2 <= i) ? acc[m][2] : 0.0f;
            w.w = (j0 + 3 <= i) ? acc[m][3] : 0.0f;
            *(float4*)&S[i * 64 + j0] = w;
        }
    }
    __syncthreads();

    // load gv = softplus(beta) * v (fp16 -> fp32) into qT region
    for (int f = tid; f < 64 * 32; f += 256) {
        int row = f >> 5;
        int c4  = (f & 31) << 2;
        float bta = beta[(tok0 + row) * NHEADS + h];
        float sp  = (bta > 20.0f) ? bta : log1pf(expf(bta));
        uint2 vr = *(const uint2*)(v + base + (size_t)row * tokstride + c4);
        float2 v01 = __half22float2(*(__half2*)&vr.x);
        float2 v23 = __half22float2(*(__half2*)&vr.y);
        float4 vv = make_float4(v01.x * sp, v01.y * sp, v23.x * sp, v23.y * sp);
        *(float4*)&gvS[row * 128 + c4] = vv;
    }
    __syncthreads();

    // phase 3: O[i][:] = sum_{j<=i} S[i][j]*gv[j][:]; gate with silu(og); fp16 out
    {
        const int tx = tid & 15, ty = tid >> 4;
        const int kk0 = tx * 8, i0 = ty * 4;
        float o[4][8] = {};
        const int jend = i0 + 4;
        for (int j = 0; j < jend; j++) {
            float s0 = S[(i0+0)*64 + j];
            float s1 = S[(i0+1)*64 + j];
            float s2 = S[(i0+2)*64 + j];
            float s3 = S[(i0+3)*64 + j];
            float4 g0 = *(const float4*)&gvS[j * 128 + kk0];
            float4 g1 = *(const float4*)&gvS[j * 128 + kk0 + 4];
            const float gg[8] = {g0.x,g0.y,g0.z,g0.w,g1.x,g1.y,g1.z,g1.w};
#pragma unroll
            for (int n = 0; n < 8; n++) {
                o[0][n] += s0 * gg[n];
                o[1][n] += s1 * gg[n];
                o[2][n] += s2 * gg[n];
                o[3][n] += s3 * gg[n];
            }
        }
#pragma unroll
        for (int m = 0; m < 4; m++) {
            const size_t roff = base + (size_t)(i0 + m) * tokstride + kk0;
            uint2 ogr0 = *(const uint2*)(og + roff);
            uint2 ogr1 = *(const uint2*)(og + roff + 4);
            float2 ga = __half22float2(*(__half2*)&ogr0.x);
            float2 gb = __half22float2(*(__half2*)&ogr0.y);
            float2 gc = __half22float2(*(__half2*)&ogr1.x);
            float2 gd = __half22float2(*(__half2*)&ogr1.y);
            const float gx[8] = {ga.x, ga.y, gb.x, gb.y, gc.x, gc.y, gd.x, gd.y};
            float y[8];
#pragma unroll
            for (int n = 0; n < 8; n++)
                y[n] = o[m][n] * (gx[n] / (1.0f + expf(-gx[n])));
            uint2 p0 = pack4h(y[0], y[1], y[2], y[3]);
            uint2 p1 = pack4h(y[4], y[5], y[6], y[7]);
            *(uint2*)(outa + roff)     = p0;
            *(uint2*)(outa + roff + 4) = p1;
        }
    }
}

// ---------------------------------------------------------------------------
extern "C" void kernel_launch(void* const* d_in, const int* in_sizes, int n_in,
                              void* d_out, int out_size)
{
    const float* hs   = (const float*)d_in[0];
    const float* q_w  = (const float*)d_in[1];
    const float* q_b  = (const float*)d_in[2];
    const float* k_w  = (const float*)d_in[3];
    const float* k_b  = (const float*)d_in[4];
    const float* v_w  = (const float*)d_in[5];
    const float* v_b  = (const float*)d_in[6];
    /* a_w, a_b (d_in[7], d_in[8]) are dead code in the reference */
    const float* b_w  = (const float*)d_in[9];
    const float* b_b  = (const float*)d_in[10];
    const float* og_w = (const float*)d_in[11];
    const float* o_w  = (const float*)d_in[12];
    const float* o_b  = (const float*)d_in[13];
    float* out = (float*)d_out;

    float *gbeta;
    __half *gq, *gk, *gv, *gog, *ga1, *gwq, *gwk, *gwv, *gwog, *gwo;
    cudaGetSymbolAddress((void**)&gq,    g_q);
    cudaGetSymbolAddress((void**)&gk,    g_k);
    cudaGetSymbolAddress((void**)&gv,    g_v);
    cudaGetSymbolAddress((void**)&gog,   g_og);
    cudaGetSymbolAddress((void**)&gbeta, g_beta);
    cudaGetSymbolAddress((void**)&ga1,   g_a1);
    cudaGetSymbolAddress((void**)&gwq,   g_wq);
    cudaGetSymbolAddress((void**)&gwk,   g_wk);
    cudaGetSymbolAddress((void**)&gwv,   g_wv);
    cudaGetSymbolAddress((void**)&gwog,  g_wog);
    cudaGetSymbolAddress((void**)&gwo,   g_wo);

    cudaFuncSetAttribute(gemm_f16<__half>,
                         cudaFuncAttributeMaxDynamicSharedMemorySize, GSMEM);
    cudaFuncSetAttribute(gemm_f16<float>,
                         cudaFuncAttributeMaxDynamicSharedMemorySize, GSMEM);

    const dim3 gG(QKV / 128, MROWS / 128);        // (16, 128)
    const unsigned wBlocks = (unsigned)((size_t)QKV * HID / 4 / 256);   // 4096

    // launch 0: beta GEMM + fused fp16 activation convert
    beta_gemm<<<MROWS / 8, 256>>>(hs, b_w, b_b, gbeta, ga1);

    // launch 1: all 5 weight converts
    wconv5<<<dim3(wBlocks, 5), 256>>>(q_w, k_w, v_w, og_w, o_w,
                                      gwq, gwk, gwv, gwog, gwo);

    // launches 2-5: projection GEMMs (fp16 outputs)
    gemm_f16<__half><<<gG, 256, GSMEM>>>(ga1, gwq,  q_b,    gq);
    gemm_f16<__half><<<gG, 256, GSMEM>>>(ga1, gwk,  k_b,    gk);
    gemm_f16<__half><<<gG, 256, GSMEM>>>(ga1, gwv,  v_b,    gv);
    gemm_f16<__half><<<gG, 256, GSMEM>>>(ga1, gwog, nullptr, gog);

    // launch 6: fused attention (+l2norm, +softplus, +silu gate, fp16 out -> ga1)
    size_t smemA = (size_t)(2 * 128 * QK_PAD + 64 * 64) * sizeof(float);
    cudaFuncSetAttribute(attn_kernel,
                         cudaFuncAttributeMaxDynamicSharedMemorySize, (int)smemA);
    dim3 gAttn(NHEADS, SEQ / CHUNK, BATCH);
    attn_kernel<<<gAttn, 256, smemA>>>(gq, gk, gv, gog, gbeta, ga1);

    // launch 7: output projection (fp32 out)
    gemm_f16<float><<<gG, 256, GSMEM>>>(ga1, gwo, o_b, out);
}

// round 13
// speedup vs baseline: 14.5286x; 1.1443x over previous
#include <cuda_runtime.h>
#include <cuda_fp16.h>
#include <math.h>
#include <stdint.h>

#define NHEADS 16
#define HDIM   128
#define CHUNK  64
#define BATCH  4
#define SEQ    4096
#define HID    2048
#define MROWS  (BATCH*SEQ)            /* 16384 */
#define QKV    (NHEADS*HDIM)          /* 2048  */

// ---------------- scratch (device globals; no allocation allowed) -----------
static __device__ __half g_q  [(size_t)MROWS*QKV];
static __device__ __half g_k  [(size_t)MROWS*QKV];
static __device__ __half g_v  [(size_t)MROWS*QKV];
static __device__ __half g_og [(size_t)MROWS*QKV];
static __device__ float  g_beta[(size_t)MROWS*NHEADS];
static __device__ __half g_a1 [(size_t)MROWS*HID];     // fp16 activations
static __device__ __half g_wq [(size_t)QKV*HID];
static __device__ __half g_wk [(size_t)QKV*HID];
static __device__ __half g_wv [(size_t)QKV*HID];
static __device__ __half g_wog[(size_t)QKV*HID];
static __device__ __half g_wo [(size_t)QKV*HID];

// ---------------- PTX helpers (family-PTX-safe: sm_80-era only) -------------
__device__ __forceinline__ uint32_t smem_u32(const void* p) {
    uint32_t a;
    asm("{ .reg .u64 t; cvta.to.shared.u64 t, %1; cvt.u32.u64 %0, t; }"
        : "=r"(a) : "l"(p));
    return a;
}
__device__ __forceinline__ void cpa16(uint32_t d, const void* s) {
    asm volatile("cp.async.cg.shared.global [%0], [%1], 16;" :: "r"(d), "l"(s));
}
__device__ __forceinline__ void cp_commit() {
    asm volatile("cp.async.commit_group;" ::: "memory");
}
__device__ __forceinline__ void cp_wait1() {
    asm volatile("cp.async.wait_group 1;" ::: "memory");
}
__device__ __forceinline__ void ldsm4(uint32_t& r0, uint32_t& r1,
                                      uint32_t& r2, uint32_t& r3, uint32_t a) {
    asm volatile("ldmatrix.sync.aligned.m8n8.x4.shared.b16 {%0,%1,%2,%3}, [%4];"
                 : "=r"(r0), "=r"(r1), "=r"(r2), "=r"(r3) : "r"(a));
}
__device__ __forceinline__ void mma16816(float* c, const uint32_t* a,
                                         uint32_t b0, uint32_t b1) {
    asm volatile(
        "mma.sync.aligned.m16n8k16.row.col.f32.f16.f16.f32 "
        "{%0,%1,%2,%3}, {%4,%5,%6,%7}, {%8,%9}, {%0,%1,%2,%3};"
        : "+f"(c[0]), "+f"(c[1]), "+f"(c[2]), "+f"(c[3])
        : "r"(a[0]), "r"(a[1]), "r"(a[2]), "r"(a[3]), "r"(b0), "r"(b1));
}

// typed pair-store: fp32 or fp16 output
__device__ __forceinline__ void st2(float* p, float x, float y) {
    *(float2*)p = make_float2(x, y);
}
__device__ __forceinline__ void st2(__half* p, float x, float y) {
    *(__half2*)p = __floats2half2_rn(x, y);
}

// ---------------------------------------------------------------------------
// mma.sync fp16 GEMM: C[M,2048] = A[M,2048] @ W[2048,2048]^T (+bias)
// CTA tile 128x128, 256 threads (8 warps, warp tile 64x32).
// 32 chunks of 64 k-cols; stage = A 16KB + W 16KB = 32KB; 3-stage cp.async
// pipeline (96KB smem) -> 2 CTAs/SM.  One __syncthreads per chunk.
// ---------------------------------------------------------------------------
#define NSC       32
#define OFF_A     0
#define OFF_W     16384
#define STG_BYTES 32768
#define GSMEM     (3*STG_BYTES)          /* 98304 */

template <typename OutT>
__global__ __launch_bounds__(256, 2)
void gemm_f16(const __half* __restrict__ A, const __half* __restrict__ W,
              const float* __restrict__ bias, OutT* __restrict__ C)
{
    extern __shared__ __align__(1024) char smem[];
    const uint32_t sb = smem_u32(smem);
    const int tid = threadIdx.x;
    const int bn0 = blockIdx.x * 128;
    const int bm0 = blockIdx.y * 128;

    const int r0  = tid >> 3;             // 0..31
    const int c16 = (tid & 7) * 16;
    const size_t rowHB = (size_t)HID * 2;

    const char* abase = (const char*)A + (size_t)bm0 * rowHB + c16;
    const char* wbase = (const char*)W + (size_t)bn0 * rowHB + c16;

    auto load_stage = [&](int sc, int s) {
        const uint32_t st = sb + s * STG_BYTES;
        const char* ap = abase + (size_t)sc * 128;
        const char* wp = wbase + (size_t)sc * 128;
#pragma unroll
        for (int i = 0; i < 4; i++) {
            const int row = r0 + i * 32;
            uint32_t off = (uint32_t)row * 128 + (uint32_t)c16;
            uint32_t sw  = off ^ ((off >> 3) & 0x70);
            cpa16(st + OFF_A + sw, ap + (size_t)row * rowHB);
            cpa16(st + OFF_W + sw, wp + (size_t)row * rowHB);
        }
        cp_commit();
    };

    const int lane = tid & 31;
    const int warp = tid >> 5;
    const int wm = warp >> 2;
    const int wn = warp & 3;

    const int a_row  = wm * 64 + (lane & 15);
    const int a_sel  = (lane >> 4) * 16;
    const uint32_t a_x = (uint32_t)((a_row & 7) << 4);
    const int b_row  = wn * 32 + ((lane >> 4) << 3) + (lane & 7);
    const int b_sel  = ((lane >> 3) & 1) * 16;
    const uint32_t b_x = (uint32_t)((b_row & 7) << 4);

    float acc[4][4][4];
#pragma unroll
    for (int i = 0; i < 4; i++)
#pragma unroll
        for (int j = 0; j < 4; j++)
#pragma unroll
            for (int r = 0; r < 4; r++) acc[i][j][r] = 0.0f;

    load_stage(0, 0);
    load_stage(1, 1);

    for (int sc = 0; sc < NSC; sc++) {
        const int s = sc % 3;
        cp_wait1();
        __syncthreads();

        if (sc + 2 < NSC) load_stage(sc + 2, (sc + 2) % 3);
        else              cp_commit();

        const uint32_t st = sb + s * STG_BYTES;

#pragma unroll
        for (int ks = 0; ks < 4; ks++) {
            const uint32_t kb = (uint32_t)(ks * 32);
            uint32_t b[2][4];
#pragma unroll
            for (int nb = 0; nb < 2; nb++) {
                uint32_t broff = (uint32_t)(b_row + nb * 16) * 128
                               + ((kb + (uint32_t)b_sel) ^ b_x);
                ldsm4(b[nb][0], b[nb][1], b[nb][2], b[nb][3], st + OFF_W + broff);
            }
#pragma unroll
            for (int mf = 0; mf < 4; mf++) {
                uint32_t aroff = (uint32_t)(a_row + mf * 16) * 128
                               + ((kb + (uint32_t)a_sel) ^ a_x);
                uint32_t a[4];
                ldsm4(a[0], a[1], a[2], a[3], st + OFF_A + aroff);
                mma16816(acc[mf][0], a, b[0][0], b[0][1]);
                mma16816(acc[mf][1], a, b[0][2], b[0][3]);
                mma16816(acc[mf][2], a, b[1][0], b[1][1]);
                mma16816(acc[mf][3], a, b[1][2], b[1][3]);
            }
        }
    }

#pragma unroll
    for (int nf = 0; nf < 4; nf++) {
        const int col = bn0 + wn * 32 + nf * 8 + (lane & 3) * 2;
        float b0 = 0.0f, b1 = 0.0f;
        if (bias) { b0 = bias[col]; b1 = bias[col + 1]; }
#pragma unroll
        for (int mf = 0; mf < 4; mf++) {
            const int row = bm0 + wm * 64 + mf * 16 + (lane >> 2);
            st2(C + (size_t)row * QKV + col,       acc[mf][nf][0] + b0,
                                                   acc[mf][nf][1] + b1);
            st2(C + (size_t)(row + 8) * QKV + col, acc[mf][nf][2] + b0,
                                                   acc[mf][nf][3] + b1);
        }
    }
}

// ---------------------------------------------------------------------------
__device__ __forceinline__ uint2 pack4h(float x, float y, float z, float w) {
    __half2 a = __floats2half2_rn(x, y);
    __half2 b = __floats2half2_rn(z, w);
    uint2 r;
    r.x = *(uint32_t*)&a;
    r.y = *(uint32_t*)&b;
    return r;
}

// all 5 weight matrices fp32 -> fp16 in one launch (blockIdx.y selects tensor)
__global__ __launch_bounds__(256)
void wconv5(const float* __restrict__ w0, const float* __restrict__ w1,
            const float* __restrict__ w2, const float* __restrict__ w3,
            const float* __restrict__ w4,
            __half* __restrict__ o0, __half* __restrict__ o1,
            __half* __restrict__ o2, __half* __restrict__ o3,
            __half* __restrict__ o4)
{
    const float* in;
    __half* out;
    switch (blockIdx.y) {
        case 0: in = w0; out = o0; break;
        case 1: in = w1; out = o1; break;
        case 2: in = w2; out = o2; break;
        case 3: in = w3; out = o3; break;
        default: in = w4; out = o4; break;
    }
    size_t i = ((size_t)blockIdx.x * 256 + threadIdx.x) * 4;
    float4 v = *(const float4*)(in + i);
    *(uint2*)(out + i) = pack4h(v.x, v.y, v.z, v.w);
}

// ---------------------------------------------------------------------------
// beta = hs @ b_w^T + b_b  (N=16), fp32; ALSO emits fp16 copy of hs.
// ---------------------------------------------------------------------------
__global__ __launch_bounds__(256)
void beta_gemm(const float* __restrict__ hs, const float* __restrict__ bw,
               const float* __restrict__ bb, float* __restrict__ beta,
               __half* __restrict__ a16)
{
    int warp = (blockIdx.x * blockDim.x + threadIdx.x) >> 5;
    int lane = threadIdx.x & 31;
    if (warp >= MROWS) return;
    const float* x = hs + (size_t)warp * HID;
    __half* xo = a16 + (size_t)warp * HID;

    float acc[NHEADS];
#pragma unroll
    for (int j = 0; j < NHEADS; j++) acc[j] = 0.0f;

    for (int t = 0; t < HID / 128; t++) {
        int k = t * 128 + lane * 4;
        float4 xv = *(const float4*)(x + k);
        *(uint2*)(xo + k) = pack4h(xv.x, xv.y, xv.z, xv.w);
#pragma unroll
        for (int j = 0; j < NHEADS; j++) {
            float4 wv = *(const float4*)(bw + (size_t)j * HID + k);
            acc[j] += xv.x*wv.x + xv.y*wv.y + xv.z*wv.z + xv.w*wv.w;
        }
    }
#pragma unroll
    for (int j = 0; j < NHEADS; j++)
#pragma unroll
        for (int off = 16; off > 0; off >>= 1)
            acc[j] += __shfl_xor_sync(0xffffffffu, acc[j], off);

    if (lane < NHEADS) {
        float v = 0.0f;
#pragma unroll
        for (int j = 0; j < NHEADS; j++) if (lane == j) v = acc[j];
        beta[(size_t)warp * NHEADS + lane] = v + bb[lane];
    }
}

// ---------------------------------------------------------------------------
// Chunk attention v2:
//   Phase 2 (QK^T) on tensor cores: S = (q.k) * fq_i * fk_j — raw fp16 q,k
//   are exact, so HMMA + fp32 post-scale adds NO new rounding vs fp32 FMA.
//   Phase 3 (S@GV) stays fp32 FMA (error-neutral).
//   Padded 272B smem rows (bank step 4) -> conflict-free ldsm, no swizzle.
//   Fully-masked warp tiles (w1,w3) skip MMA and zero-fill.
//   smem 52.7KB -> up to 4 CTAs/SM.
// ---------------------------------------------------------------------------
#define ATT_KS     17408              /* byte offset of k tile   */
#define ATT_FQ     34816
#define ATT_FK     35072
#define ATT_S      35328              /* fp32 S [64][68]         */
#define ATT_SMEM   52736
#define QROW_B     272                /* 128 fp16 + 8 pad = 272B */

__global__ __launch_bounds__(256)
void attn_kernel(const __half* __restrict__ q, const __half* __restrict__ k,
                 const __half* __restrict__ v, const __half* __restrict__ og,
                 const float* __restrict__ beta, __half* __restrict__ outa)
{
    extern __shared__ __align__(1024) char smraw[];
    float* fq  = (float*)(smraw + ATT_FQ);
    float* fk  = (float*)(smraw + ATT_FK);
    float* S   = (float*)(smraw + ATT_S);      // stride 68 floats
    float* gvS = (float*)smraw;                // [64][128] fp32 (reuses q/k)
    const uint32_t qsB = smem_u32(smraw);
    const uint32_t ksB = qsB + ATT_KS;

    const int h  = blockIdx.x;
    const int cn = blockIdx.y;
    const int b  = blockIdx.z;
    const int tid = threadIdx.x;
    const int lane = tid & 31;
    const int warp = tid >> 5;

    const size_t tok0 = (size_t)b * SEQ + (size_t)cn * CHUNK;
    const size_t base = (tok0 * NHEADS + h) * HDIM;
    const int tokstride = NHEADS * HDIM;       // 2048
    const float eps_n = 1.1313708499e-11f;     // sqrt(128) * 1e-12

    // ---- phase 1: copy raw fp16 q,k to padded smem; compute 1/norm ----
    for (int f = tid; f < 64 * 32; f += 256) {
        int row = f >> 5;            // warp-uniform
        int l8  = f & 31;            // 8-byte unit within row
        size_t g = base + (size_t)row * tokstride + l8 * 4;
        uint2 qr = *(const uint2*)(q + g);
        uint2 kr = *(const uint2*)(k + g);

        float2 q01 = __half22float2(*(__half2*)&qr.x);
        float2 q23 = __half22float2(*(__half2*)&qr.y);
        float2 k01 = __half22float2(*(__half2*)&kr.x);
        float2 k23 = __half22float2(*(__half2*)&kr.y);
        float sq = q01.x*q01.x + q01.y*q01.y + q23.x*q23.x + q23.y*q23.y;
        float sk = k01.x*k01.x + k01.y*k01.y + k23.x*k23.x + k23.y*k23.y;
#pragma unroll
        for (int off = 16; off > 0; off >>= 1) {
            sq += __shfl_xor_sync(0xffffffffu, sq, off);
            sk += __shfl_xor_sync(0xffffffffu, sk, off);
        }
        *(uint2*)(smraw + row * QROW_B + l8 * 8)          = qr;
        *(uint2*)(smraw + ATT_KS + row * QROW_B + l8 * 8) = kr;
        if (lane == 0) {
            fq[row] = 1.0f / fmaxf(sqrtf(sq), eps_n);
            fk[row] = 1.0f / fmaxf(sqrtf(sk), eps_n);
        }
    }
    __syncthreads();

    // ---- phase 2: S = tril( (q.k) * fq_i * fk_j ) via HMMA ----
    {
        const int m0 = (warp >> 1) * 16;
        const int n0 = (warp & 1) * 32;
        if (n0 > m0 + 15) {
            // fully masked tile: zero-fill
            for (int idx = lane; idx < 512; idx += 32) {
                int r = m0 + (idx >> 5);
                int j = n0 + (idx & 31);
                S[r * 68 + j] = 0.0f;
            }
        } else {
            float acc[4][4];
#pragma unroll
            for (int t = 0; t < 4; t++)
#pragma unroll
                for (int r = 0; r < 4; r++) acc[t][r] = 0.0f;

            const uint32_t aoff = qsB + (uint32_t)(m0 + (lane & 15)) * QROW_B
                                + (uint32_t)((lane >> 4) * 16);
            const int brow = n0 + ((lane >> 4) << 3) + (lane & 7);
            const uint32_t boff0 = ksB + (uint32_t)brow * QROW_B
                                 + (uint32_t)(((lane >> 3) & 1) * 16);
            const uint32_t boff1 = boff0 + 16u * QROW_B;

#pragma unroll
            for (int ks = 0; ks < 8; ks++) {
                const uint32_t kb = (uint32_t)(ks * 32);
                uint32_t a[4], b0[4], b1[4];
                ldsm4(a[0], a[1], a[2], a[3], aoff + kb);
                ldsm4(b0[0], b0[1], b0[2], b0[3], boff0 + kb);
                ldsm4(b1[0], b1[1], b1[2], b1[3], boff1 + kb);
                mma16816(acc[0], a, b0[0], b0[1]);
                mma16816(acc[1], a, b0[2], b0[3]);
                mma16816(acc[2], a, b1[0], b1[1]);
                mma16816(acc[3], a, b1[2], b1[3]);
            }

            const int r0 = m0 + (lane >> 2);
            const int r1 = r0 + 8;
            const float fq0 = fq[r0], fq1 = fq[r1];
#pragma unroll
            for (int t = 0; t < 4; t++) {
                const int j0 = n0 + t * 8 + (lane & 3) * 2;
                const int j1 = j0 + 1;
                const float fk0 = fk[j0], fk1 = fk[j1];
                S[r0 * 68 + j0] = (j0 <= r0) ? acc[t][0] * fq0 * fk0 : 0.0f;
                S[r0 * 68 + j1] = (j1 <= r0) ? acc[t][1] * fq0 * fk1 : 0.0f;
                S[r1 * 68 + j0] = (j0 <= r1) ? acc[t][2] * fq1 * fk0 : 0.0f;
                S[r1 * 68 + j1] = (j1 <= r1) ? acc[t][3] * fq1 * fk1 : 0.0f;
            }
        }
    }
    __syncthreads();

    // ---- load gv = softplus(beta) * v into the q/k smem region (fp32) ----
    for (int f = tid; f < 64 * 32; f += 256) {
        int row = f >> 5;
        int c4  = (f & 31) << 2;
        float bta = beta[(tok0 + row) * NHEADS + h];
        float sp  = (bta > 20.0f) ? bta : log1pf(expf(bta));
        uint2 vr = *(const uint2*)(v + base + (size_t)row * tokstride + c4);
        float2 v01 = __half22float2(*(__half2*)&vr.x);
        float2 v23 = __half22float2(*(__half2*)&vr.y);
        float4 vv = make_float4(v01.x * sp, v01.y * sp, v23.x * sp, v23.y * sp);
        *(float4*)&gvS[row * 128 + c4] = vv;
    }
    __syncthreads();

    // ---- phase 3: O[i][:] = sum_{j<=i} S[i][j]*gv[j][:]; silu(og) gate ----
    {
        const int tx = tid & 15, ty = tid >> 4;
        const int kk0 = tx * 8, i0 = ty * 4;
        float o[4][8] = {};
        const int jend = i0 + 4;
        for (int j = 0; j < jend; j++) {
            float s0 = S[(i0+0)*68 + j];
            float s1 = S[(i0+1)*68 + j];
            float s2 = S[(i0+2)*68 + j];
            float s3 = S[(i0+3)*68 + j];
            float4 g0 = *(const float4*)&gvS[j * 128 + kk0];
            float4 g1 = *(const float4*)&gvS[j * 128 + kk0 + 4];
            const float gg[8] = {g0.x,g0.y,g0.z,g0.w,g1.x,g1.y,g1.z,g1.w};
#pragma unroll
            for (int n = 0; n < 8; n++) {
                o[0][n] += s0 * gg[n];
                o[1][n] += s1 * gg[n];
                o[2][n] += s2 * gg[n];
                o[3][n] += s3 * gg[n];
            }
        }
#pragma unroll
        for (int m = 0; m < 4; m++) {
            const size_t roff = base + (size_t)(i0 + m) * tokstride + kk0;
            uint2 ogr0 = *(const uint2*)(og + roff);
            uint2 ogr1 = *(const uint2*)(og + roff + 4);
            float2 ga = __half22float2(*(__half2*)&ogr0.x);
            float2 gb = __half22float2(*(__half2*)&ogr0.y);
            float2 gc = __half22float2(*(__half2*)&ogr1.x);
            float2 gd = __half22float2(*(__half2*)&ogr1.y);
            const float gx[8] = {ga.x, ga.y, gb.x, gb.y, gc.x, gc.y, gd.x, gd.y};
            float y[8];
#pragma unroll
            for (int n = 0; n < 8; n++)
                y[n] = o[m][n] * (gx[n] / (1.0f + expf(-gx[n])));
            uint2 p0 = pack4h(y[0], y[1], y[2], y[3]);
            uint2 p1 = pack4h(y[4], y[5], y[6], y[7]);
            *(uint2*)(outa + roff)     = p0;
            *(uint2*)(outa + roff + 4) = p1;
        }
    }
}

// ---------------------------------------------------------------------------
extern "C" void kernel_launch(void* const* d_in, const int* in_sizes, int n_in,
                              void* d_out, int out_size)
{
    const float* hs   = (const float*)d_in[0];
    const float* q_w  = (const float*)d_in[1];
    const float* q_b  = (const float*)d_in[2];
    const float* k_w  = (const float*)d_in[3];
    const float* k_b  = (const float*)d_in[4];
    const float* v_w  = (const float*)d_in[5];
    const float* v_b  = (const float*)d_in[6];
    /* a_w, a_b (d_in[7], d_in[8]) are dead code in the reference */
    const float* b_w  = (const float*)d_in[9];
    const float* b_b  = (const float*)d_in[10];
    const float* og_w = (const float*)d_in[11];
    const float* o_w  = (const float*)d_in[12];
    const float* o_b  = (const float*)d_in[13];
    float* out = (float*)d_out;

    float *gbeta;
    __half *gq, *gk, *gv, *gog, *ga1, *gwq, *gwk, *gwv, *gwog, *gwo;
    cudaGetSymbolAddress((void**)&gq,    g_q);
    cudaGetSymbolAddress((void**)&gk,    g_k);
    cudaGetSymbolAddress((void**)&gv,    g_v);
    cudaGetSymbolAddress((void**)&gog,   g_og);
    cudaGetSymbolAddress((void**)&gbeta, g_beta);
    cudaGetSymbolAddress((void**)&ga1,   g_a1);
    cudaGetSymbolAddress((void**)&gwq,   g_wq);
    cudaGetSymbolAddress((void**)&gwk,   g_wk);
    cudaGetSymbolAddress((void**)&gwv,   g_wv);
    cudaGetSymbolAddress((void**)&gwog,  g_wog);
    cudaGetSymbolAddress((void**)&gwo,   g_wo);

    cudaFuncSetAttribute(gemm_f16<__half>,
                         cudaFuncAttributeMaxDynamicSharedMemorySize, GSMEM);
    cudaFuncSetAttribute(gemm_f16<float>,
                         cudaFuncAttributeMaxDynamicSharedMemorySize, GSMEM);
    cudaFuncSetAttribute(attn_kernel,
                         cudaFuncAttributeMaxDynamicSharedMemorySize, ATT_SMEM);

    const dim3 gG(QKV / 128, MROWS / 128);        // (16, 128)
    const unsigned wBlocks = (unsigned)((size_t)QKV * HID / 4 / 256);   // 4096

    // launch 0: beta GEMM + fused fp16 activation convert
    beta_gemm<<<MROWS / 8, 256>>>(hs, b_w, b_b, gbeta, ga1);

    // launch 1: all 5 weight converts
    wconv5<<<dim3(wBlocks, 5), 256>>>(q_w, k_w, v_w, og_w, o_w,
                                      gwq, gwk, gwv, gwog, gwo);

    // launches 2-5: projection GEMMs (fp16 outputs)
    gemm_f16<__half><<<gG, 256, GSMEM>>>(ga1, gwq,  q_b,    gq);
    gemm_f16<__half><<<gG, 256, GSMEM>>>(ga1, gwk,  k_b,    gk);
    gemm_f16<__half><<<gG, 256, GSMEM>>>(ga1, gwv,  v_b,    gv);
    gemm_f16<__half><<<gG, 256, GSMEM>>>(ga1, gwog, nullptr, gog);

    // launch 6: fused attention (HMMA phase-2, fp32 phase-3, silu gate)
    dim3 gAttn(NHEADS, SEQ / CHUNK, BATCH);
    attn_kernel<<<gAttn, 256, ATT_SMEM>>>(gq, gk, gv, gog, gbeta, ga1);

    // launch 7: output projection (fp32 out)
    gemm_f16<float><<<gG, 256, GSMEM>>>(ga1, gwo, o_b, out);
}